// round 3
// baseline (speedup 1.0000x reference)
#include <cuda_runtime.h>
#include <math.h>
#include <stdint.h>

#define NTOK 3072
#define DIM  768
#define NHEAD 12
#define HDIM 64

// ---------------- static device scratch ----------------
__device__ float g_qa[NTOK * DIM];
__device__ float g_ka[NTOK * DIM];
__device__ float g_Q [NTOK * DIM];
__device__ float g_K [NTOK * DIM];
__device__ float g_V [NTOK * DIM];
__device__ float g_O [NTOK * DIM];
__device__ float g_S [(size_t)NTOK * NTOK];            // scores / attn
__device__ float g_Sh[(size_t)NHEAD * NTOK * NTOK];    // per-head logits
__device__ float g_Wf[(size_t)NTOK * NTOK];            // fused weights
__device__ double g_stats[2];

// ---------------- helpers ----------------
__device__ __forceinline__ float warp_max(float v) {
    #pragma unroll
    for (int o = 16; o; o >>= 1) v = fmaxf(v, __shfl_xor_sync(0xffffffffu, v, o));
    return v;
}
__device__ __forceinline__ float warp_sum(float v) {
    #pragma unroll
    for (int o = 16; o; o >>= 1) v += __shfl_xor_sync(0xffffffffu, v, o);
    return v;
}
__device__ __forceinline__ void mma_tf32(float* d, const uint32_t* a, const uint32_t* b) {
    asm volatile(
        "mma.sync.aligned.m16n8k8.row.col.f32.tf32.tf32.f32 "
        "{%0,%1,%2,%3}, {%4,%5,%6,%7}, {%8,%9}, {%0,%1,%2,%3};\n"
        : "+f"(d[0]), "+f"(d[1]), "+f"(d[2]), "+f"(d[3])
        : "r"(a[0]), "r"(a[1]), "r"(a[2]), "r"(a[3]), "r"(b[0]), "r"(b[1]));
}
__device__ __forceinline__ void cpa16(uint32_t smem, const void* gptr) {
    asm volatile("cp.async.ca.shared.global [%0], [%1], 16;\n" :: "r"(smem), "l"(gptr));
}
#define CP_COMMIT()  asm volatile("cp.async.commit_group;\n")
#define CP_WAIT(N)   asm volatile("cp.async.wait_group %0;\n" :: "n"(N))

#define ASTR 20    // smem stride for [row][k16] tiles: conflict-free fragment LDS
#define BSTR 136   // smem stride for [k16][col128] tiles (NN B)

// ---------------- tf32 tensor-core NT GEMM: C = scale*A.B^T (+bias), batched ----------------
// A row-major M x K (lda), B row-major N x K (ldb). Tile 128x128x16, 8 warps (4x2),
// cp.async double-buffered, raw fp32 bits fed to mma.tf32 (hw truncation).
__global__ __launch_bounds__(256, 2) void gemm_nt_tc(
    const float* __restrict__ A, int lda, long long strideA,
    const float* __restrict__ B, int ldb, long long strideB,
    float* __restrict__ C, int ldc, long long strideC,
    int K, const float* __restrict__ bias, float scale)
{
    __shared__ float As[2][128 * ASTR];
    __shared__ float Bs[2][128 * ASTR];

    const int z = blockIdx.z;
    A += (size_t)z * strideA;
    B += (size_t)z * strideB;
    C += (size_t)z * strideC;

    const int tid = threadIdx.x;
    const int row0 = blockIdx.y * 128, col0 = blockIdx.x * 128;
    const int wid = tid >> 5, lane = tid & 31;
    const int wm = wid & 3, wn = wid >> 2;   // 4 x 2 warp grid
    const int g = lane >> 2, tig = lane & 3;

    float acc[2][8][4];
    #pragma unroll
    for (int i = 0; i < 2; i++)
        #pragma unroll
        for (int j = 0; j < 8; j++)
            #pragma unroll
            for (int q = 0; q < 4; q++) acc[i][j][q] = 0.f;

    // chunk mapping: 512 x 16B chunks per tile, 2 per thread
    const int c0 = tid * 2;          // first chunk id
    const int cr0 = c0 >> 2, cs0 = (c0 & 3) * 4;
    const int cr1 = (c0 + 1) >> 2, cs1 = ((c0 + 1) & 3) * 4;

    const uint32_t sA = (uint32_t)__cvta_generic_to_shared(&As[0][0]);
    const uint32_t sB = (uint32_t)__cvta_generic_to_shared(&Bs[0][0]);
    const uint32_t stgB = 128 * ASTR * 4;  // stage stride in bytes

    const float* gA0 = A + (size_t)(row0 + cr0) * lda + cs0;
    const float* gA1 = A + (size_t)(row0 + cr1) * lda + cs1;
    const float* gB0 = B + (size_t)(col0 + cr0) * ldb + cs0;
    const float* gB1 = B + (size_t)(col0 + cr1) * ldb + cs1;
    const uint32_t dA0 = sA + (cr0 * ASTR + cs0) * 4;
    const uint32_t dA1 = sA + (cr1 * ASTR + cs1) * 4;
    const uint32_t dB0 = sB + (cr0 * ASTR + cs0) * 4;
    const uint32_t dB1 = sB + (cr1 * ASTR + cs1) * 4;

    const int niter = K >> 4;

    // prologue: stage 0
    cpa16(dA0, gA0); cpa16(dA1, gA1);
    cpa16(dB0, gB0); cpa16(dB1, gB1);
    CP_COMMIT();

    for (int it = 0; it < niter; ++it) {
        if (it + 1 < niter) {
            const int st = (it + 1) & 1;
            const int k0 = (it + 1) << 4;
            cpa16(dA0 + st * stgB, gA0 + k0); cpa16(dA1 + st * stgB, gA1 + k0);
            cpa16(dB0 + st * stgB, gB0 + k0); cpa16(dB1 + st * stgB, gB1 + k0);
            CP_COMMIT();
            CP_WAIT(1);
        } else {
            CP_WAIT(0);
        }
        __syncthreads();

        const float* as = As[it & 1];
        const float* bs = Bs[it & 1];
        #pragma unroll
        for (int kk = 0; kk < 16; kk += 8) {
            uint32_t af[2][4];
            #pragma unroll
            for (int mi = 0; mi < 2; mi++) {
                int rb = wm * 32 + mi * 16;
                af[mi][0] = __float_as_uint(as[(rb + g    ) * ASTR + kk + tig    ]);
                af[mi][1] = __float_as_uint(as[(rb + g + 8) * ASTR + kk + tig    ]);
                af[mi][2] = __float_as_uint(as[(rb + g    ) * ASTR + kk + tig + 4]);
                af[mi][3] = __float_as_uint(as[(rb + g + 8) * ASTR + kk + tig + 4]);
            }
            #pragma unroll
            for (int ni = 0; ni < 8; ni++) {
                int cb = wn * 64 + ni * 8;
                uint32_t bf[2];
                bf[0] = __float_as_uint(bs[(cb + g) * ASTR + kk + tig    ]);
                bf[1] = __float_as_uint(bs[(cb + g) * ASTR + kk + tig + 4]);
                #pragma unroll
                for (int mi = 0; mi < 2; mi++) mma_tf32(acc[mi][ni], af[mi], bf);
            }
        }
        __syncthreads();
    }

    #pragma unroll
    for (int mi = 0; mi < 2; mi++) {
        #pragma unroll
        for (int gg = 0; gg < 2; gg++) {
            int r = row0 + wm * 32 + mi * 16 + g + gg * 8;
            #pragma unroll
            for (int ni = 0; ni < 8; ni++) {
                int c = col0 + wn * 64 + ni * 8 + tig * 2;
                float2 v;
                v.x = acc[mi][ni][gg * 2 + 0] * scale;
                v.y = acc[mi][ni][gg * 2 + 1] * scale;
                if (bias) { v.x += bias[c]; v.y += bias[c + 1]; }
                *(float2*)(C + (size_t)r * ldc + c) = v;
            }
        }
    }
}

// ---------------- tf32 tensor-core NN GEMM: C = A @ B ----------------
__global__ __launch_bounds__(256, 2) void gemm_nn_tc(
    const float* __restrict__ A, int lda,
    const float* __restrict__ B, int ldb,
    float* __restrict__ C, int ldc, int K)
{
    __shared__ float As[2][128 * ASTR];
    __shared__ float Bs[2][16 * BSTR];

    const int tid = threadIdx.x;
    const int row0 = blockIdx.y * 128, col0 = blockIdx.x * 128;
    const int wid = tid >> 5, lane = tid & 31;
    const int wm = wid & 3, wn = wid >> 2;
    const int g = lane >> 2, tig = lane & 3;

    float acc[2][8][4];
    #pragma unroll
    for (int i = 0; i < 2; i++)
        #pragma unroll
        for (int j = 0; j < 8; j++)
            #pragma unroll
            for (int q = 0; q < 4; q++) acc[i][j][q] = 0.f;

    const int c0 = tid * 2;
    const int ar0 = c0 >> 2, as0 = (c0 & 3) * 4;
    const int ar1 = (c0 + 1) >> 2, as1 = ((c0 + 1) & 3) * 4;
    const int bk0 = c0 >> 5, bs0 = (c0 & 31) * 4;      // B: 32 chunks per k-row
    const int bk1 = (c0 + 1) >> 5, bs1 = ((c0 + 1) & 31) * 4;

    const uint32_t sA = (uint32_t)__cvta_generic_to_shared(&As[0][0]);
    const uint32_t sB = (uint32_t)__cvta_generic_to_shared(&Bs[0][0]);
    const uint32_t stgA = 128 * ASTR * 4;
    const uint32_t stgBB = 16 * BSTR * 4;

    const float* gA0 = A + (size_t)(row0 + ar0) * lda + as0;
    const float* gA1 = A + (size_t)(row0 + ar1) * lda + as1;
    const float* gB0 = B + (size_t)bk0 * ldb + col0 + bs0;
    const float* gB1 = B + (size_t)bk1 * ldb + col0 + bs1;
    const uint32_t dA0 = sA + (ar0 * ASTR + as0) * 4;
    const uint32_t dA1 = sA + (ar1 * ASTR + as1) * 4;
    const uint32_t dB0 = sB + (bk0 * BSTR + bs0) * 4;
    const uint32_t dB1 = sB + (bk1 * BSTR + bs1) * 4;

    const int niter = K >> 4;

    cpa16(dA0, gA0); cpa16(dA1, gA1);
    cpa16(dB0, gB0); cpa16(dB1, gB1);
    CP_COMMIT();

    for (int it = 0; it < niter; ++it) {
        if (it + 1 < niter) {
            const int st = (it + 1) & 1;
            const long long k0 = (long long)(it + 1) << 4;
            cpa16(dA0 + st * stgA, gA0 + k0);
            cpa16(dA1 + st * stgA, gA1 + k0);
            cpa16(dB0 + st * stgBB, gB0 + k0 * ldb);
            cpa16(dB1 + st * stgBB, gB1 + k0 * ldb);
            CP_COMMIT();
            CP_WAIT(1);
        } else {
            CP_WAIT(0);
        }
        __syncthreads();

        const float* as = As[it & 1];
        const float* bs = Bs[it & 1];
        #pragma unroll
        for (int kk = 0; kk < 16; kk += 8) {
            uint32_t af[2][4];
            #pragma unroll
            for (int mi = 0; mi < 2; mi++) {
                int rb = wm * 32 + mi * 16;
                af[mi][0] = __float_as_uint(as[(rb + g    ) * ASTR + kk + tig    ]);
                af[mi][1] = __float_as_uint(as[(rb + g + 8) * ASTR + kk + tig    ]);
                af[mi][2] = __float_as_uint(as[(rb + g    ) * ASTR + kk + tig + 4]);
                af[mi][3] = __float_as_uint(as[(rb + g + 8) * ASTR + kk + tig + 4]);
            }
            #pragma unroll
            for (int ni = 0; ni < 8; ni++) {
                int cb = wn * 64 + ni * 8;
                uint32_t bf[2];
                bf[0] = __float_as_uint(bs[(kk + tig    ) * BSTR + cb + g]);
                bf[1] = __float_as_uint(bs[(kk + tig + 4) * BSTR + cb + g]);
                #pragma unroll
                for (int mi = 0; mi < 2; mi++) mma_tf32(acc[mi][ni], af[mi], bf);
            }
        }
        __syncthreads();
    }

    #pragma unroll
    for (int mi = 0; mi < 2; mi++) {
        #pragma unroll
        for (int gg = 0; gg < 2; gg++) {
            int r = row0 + wm * 32 + mi * 16 + g + gg * 8;
            #pragma unroll
            for (int ni = 0; ni < 8; ni++) {
                int c = col0 + wn * 64 + ni * 8 + tig * 2;
                float2 v;
                v.x = acc[mi][ni][gg * 2 + 0];
                v.y = acc[mi][ni][gg * 2 + 1];
                *(float2*)(C + (size_t)r * ldc + c) = v;
            }
        }
    }
}

// ---------------- fused: 12-head softmax avg + Gaussian weight + stats ----------------
__global__ void zero_stats_kernel() { g_stats[0] = 0.0; g_stats[1] = 0.0; }

extern __shared__ float sh_rows[];  // NHEAD * NTOK floats

#define HT 512  // threads in headsmax
__global__ __launch_bounds__(HT) void headsmax_wf_kernel(const float* __restrict__ dd)
{
    __shared__ float redA[16], redB[16];
    __shared__ float mh[NHEAD], invZ[NHEAD];
    const int i = blockIdx.x, tid = threadIdx.x;
    const int lane = tid & 31, wid = tid >> 5;

    #pragma unroll
    for (int h = 0; h < NHEAD; h++) {
        const float* row = g_Sh + (size_t)h * NTOK * NTOK + (size_t)i * NTOK;
        float lmax = -1e30f;
        for (int j = tid; j < NTOK; j += HT) {
            float v = row[j];
            sh_rows[h * NTOK + j] = v;
            lmax = fmaxf(lmax, v);
        }
        lmax = warp_max(lmax);
        if (lane == 0) redA[wid] = lmax;
        __syncthreads();
        if (wid == 0) {
            float t = (lane < 16) ? redA[lane] : -1e30f;
            t = warp_max(t);
            if (lane == 0) mh[h] = t;
        }
        __syncthreads();
    }

    #pragma unroll
    for (int h = 0; h < NHEAD; h++) {
        const float m = mh[h];
        float lsum = 0.f;
        for (int j = tid; j < NTOK; j += HT) {
            float e = __expf(sh_rows[h * NTOK + j] - m);
            sh_rows[h * NTOK + j] = e;
            lsum += e;
        }
        lsum = warp_sum(lsum);
        if (lane == 0) redB[wid] = lsum;
        __syncthreads();
        if (wid == 0) {
            float t = (lane < 16) ? redB[lane] : 0.f;
            t = warp_sum(t);
            if (lane == 0) invZ[h] = 1.f / (t * (float)NHEAD);
        }
        __syncthreads();
    }

    float iz[NHEAD];
    #pragma unroll
    for (int h = 0; h < NHEAD; h++) iz[h] = invZ[h];

    const float* drow = dd + (size_t)i * NTOK;
    float* frow = g_Wf + (size_t)i * NTOK;
    float s1 = 0.f, s2 = 0.f;
    for (int j = tid; j < NTOK; j += HT) {
        float wa = 0.f;
        #pragma unroll
        for (int h = 0; h < NHEAD; h++) wa += sh_rows[h * NTOK + j] * iz[h];
        float d = drow[j];
        float wf = __expf(-0.5f * d * d) * wa;
        frow[j] = wf;
        s1 += wf;
        s2 += wf * wf;
    }
    s1 = warp_sum(s1);
    s2 = warp_sum(s2);
    if (lane == 0) { redA[wid] = s1; redB[wid] = s2; }
    __syncthreads();
    if (wid == 0) {
        float a = (lane < 16) ? redA[lane] : 0.f;
        float b = (lane < 16) ? redB[lane] : 0.f;
        a = warp_sum(a);
        b = warp_sum(b);
        if (lane == 0) {
            atomicAdd(&g_stats[0], (double)a);
            atomicAdd(&g_stats[1], (double)b);
        }
    }
}

// ---------------- guided attention masked softmax (in place on g_S) ----------------
__global__ __launch_bounds__(256) void masked_softmax_kernel()
{
    __shared__ float z[NTOK];
    __shared__ float redA[8], redB[8];
    __shared__ float sh_thr;
    const int i = blockIdx.x, tid = threadIdx.x;
    const int lane = tid & 31, wid = tid >> 5;

    if (tid == 0) {
        double cnt = (double)NTOK * (double)NTOK;
        double mean = g_stats[0] / cnt;
        double var = (g_stats[1] - g_stats[0] * g_stats[0] / cnt) / (cnt - 1.0);
        if (var < 0.0) var = 0.0;
        sh_thr = (float)(mean + 0.5 * sqrt(var));
    }
    __syncthreads();
    const float thr = sh_thr;
    const float invthr = 1.f / thr;

    float* srow = g_S + (size_t)i * NTOK;
    const float* frow = g_Wf + (size_t)i * NTOK;

    float lmax = -1e30f;
    for (int j = tid; j < NTOK; j += 256) {
        float wf = frow[j];
        float ww = (wf < thr) ? wf * invthr : 1.f;
        float v = srow[j] * ww;
        z[j] = v;
        lmax = fmaxf(lmax, v);
    }
    lmax = warp_max(lmax);
    if (lane == 0) redA[wid] = lmax;
    __syncthreads();
    if (wid == 0) {
        float t = (lane < 8) ? redA[lane] : -1e30f;
        t = warp_max(t);
        if (lane == 0) redA[0] = t;
    }
    __syncthreads();
    const float m = redA[0];

    float lsum = 0.f;
    for (int j = tid; j < NTOK; j += 256) {
        float e = __expf(z[j] - m);
        z[j] = e;
        lsum += e;
    }
    lsum = warp_sum(lsum);
    if (lane == 0) redB[wid] = lsum;
    __syncthreads();
    if (wid == 0) {
        float t = (lane < 8) ? redB[lane] : 0.f;
        t = warp_sum(t);
        if (lane == 0) redB[0] = t;
    }
    __syncthreads();
    const float invs = 1.f / redB[0];

    for (int j = tid; j < NTOK; j += 256)
        srow[j] = z[j] * invs;
}

// ---------------- residual + LayerNorm ----------------
__global__ __launch_bounds__(256) void ln_kernel(
    const float* __restrict__ hs,
    const float* __restrict__ gamma,
    const float* __restrict__ beta,
    float* __restrict__ out)
{
    const int i = blockIdx.x, tid = threadIdx.x;
    const int lane = tid & 31, wid = tid >> 5;
    __shared__ float r1[8], r2[8];

    const float* orow = g_O + (size_t)i * DIM;
    const float* srow = hs + (size_t)i * DIM;

    float x[3];
    float s = 0.f, ss = 0.f;
    #pragma unroll
    for (int t = 0; t < 3; t++) {
        int c = tid + t * 256;
        x[t] = srow[c] + orow[c];
        s += x[t];
        ss += x[t] * x[t];
    }
    s = warp_sum(s);
    ss = warp_sum(ss);
    if (lane == 0) { r1[wid] = s; r2[wid] = ss; }
    __syncthreads();
    if (wid == 0) {
        float a = (lane < 8) ? r1[lane] : 0.f;
        float b = (lane < 8) ? r2[lane] : 0.f;
        a = warp_sum(a);
        b = warp_sum(b);
        if (lane == 0) { r1[0] = a; r2[0] = b; }
    }
    __syncthreads();
    const float mu = r1[0] * (1.f / DIM);
    const float var = r2[0] * (1.f / DIM) - mu * mu;
    const float inv = rsqrtf(var + 1e-5f);

    #pragma unroll
    for (int t = 0; t < 3; t++) {
        int c = tid + t * 256;
        out[(size_t)i * DIM + c] = (x[t] - mu) * inv * gamma[c] + beta[c];
    }
}

// ---------------- host ----------------
extern "C" void kernel_launch(void* const* d_in, const int* in_sizes, int n_in,
                              void* d_out, int out_size)
{
    const float* h_a  = (const float*)d_in[0];
    const float* h_s  = (const float*)d_in[1];
    const float* dep  = (const float*)d_in[2];
    const float* Wq_a = (const float*)d_in[3];
    const float* bq_a = (const float*)d_in[4];
    const float* Wk_a = (const float*)d_in[5];
    const float* bk_a = (const float*)d_in[6];
    const float* Wq   = (const float*)d_in[7];
    const float* bq   = (const float*)d_in[8];
    const float* Wk   = (const float*)d_in[9];
    const float* bk   = (const float*)d_in[10];
    const float* Wv   = (const float*)d_in[11];
    const float* bv   = (const float*)d_in[12];
    const float* lng  = (const float*)d_in[13];
    const float* lnb  = (const float*)d_in[14];
    float* out = (float*)d_out;

    float *qa, *ka, *Q, *K, *V, *O, *S, *Sh;
    cudaGetSymbolAddress((void**)&qa, g_qa);
    cudaGetSymbolAddress((void**)&ka, g_ka);
    cudaGetSymbolAddress((void**)&Q,  g_Q);
    cudaGetSymbolAddress((void**)&K,  g_K);
    cudaGetSymbolAddress((void**)&V,  g_V);
    cudaGetSymbolAddress((void**)&O,  g_O);
    cudaGetSymbolAddress((void**)&S,  g_S);
    cudaGetSymbolAddress((void**)&Sh, g_Sh);

    static int smem_set = 0;
    if (!smem_set) {
        cudaFuncSetAttribute(headsmax_wf_kernel,
                             cudaFuncAttributeMaxDynamicSharedMemorySize,
                             NHEAD * NTOK * sizeof(float));
        smem_set = 1;
    }

    const dim3 blk(256);
    const dim3 gProj(DIM / 128, NTOK / 128);          // 6 x 24
    const dim3 gNN(NTOK / 128, NTOK / 128);           // 24 x 24
    const dim3 gHeads(NTOK / 128, NTOK / 128, NHEAD); // 24 x 24 x 12

    // projections: X @ W^T + b
    gemm_nt_tc<<<gProj, blk>>>(h_a, DIM, 0, Wq_a, DIM, 0, qa, DIM, 0, DIM, bq_a, 1.f);
    gemm_nt_tc<<<gProj, blk>>>(h_a, DIM, 0, Wk_a, DIM, 0, ka, DIM, 0, DIM, bk_a, 1.f);
    gemm_nt_tc<<<gProj, blk>>>(h_s, DIM, 0, Wq,   DIM, 0, Q,  DIM, 0, DIM, bq,   1.f);
    gemm_nt_tc<<<gProj, blk>>>(h_s, DIM, 0, Wk,   DIM, 0, K,  DIM, 0, DIM, bk,   1.f);
    gemm_nt_tc<<<gProj, blk>>>(h_s, DIM, 0, Wv,   DIM, 0, V,  DIM, 0, DIM, bv,   1.f);

    // all 12 per-head logit GEMMs in one batched launch
    gemm_nt_tc<<<gHeads, blk>>>(qa, DIM, HDIM, ka, DIM, HDIM,
                                Sh, NTOK, (long long)NTOK * NTOK,
                                HDIM, nullptr, 0.125f);

    // fused 12-head softmax + average + structural weight + stats
    zero_stats_kernel<<<1, 1>>>();
    headsmax_wf_kernel<<<NTOK, HT, NHEAD * NTOK * sizeof(float)>>>(dep);

    // guided attention
    const float score_scale = 1.f / sqrtf((float)DIM);
    gemm_nt_tc<<<gNN, blk>>>(Q, DIM, 0, K, DIM, 0, S, NTOK, 0, DIM, nullptr, score_scale);
    masked_softmax_kernel<<<NTOK, 256>>>();
    gemm_nn_tc<<<gProj, blk>>>(S, NTOK, V, DIM, O, DIM, NTOK);

    // residual + LayerNorm
    ln_kernel<<<NTOK, 256>>>(h_s, lng, lnb, out);
}

// round 4
// speedup vs baseline: 1.6809x; 1.6809x over previous
#include <cuda_runtime.h>
#include <cuda_fp16.h>
#include <math.h>
#include <stdint.h>

#define NTOK 3072
#define DIM  768
#define NHEAD 12
#define HDIM 64

// ---------------- static device scratch ----------------
__device__ float  g_qa[NTOK * DIM];
__device__ float  g_ka[NTOK * DIM];
__device__ float  g_Q [NTOK * DIM];
__device__ float  g_K [NTOK * DIM];
__device__ float  g_V [NTOK * DIM];
__device__ float  g_O [NTOK * DIM];
__device__ float  g_S [(size_t)NTOK * NTOK];            // scores / attn
__device__ __half g_Sh[(size_t)NHEAD * NTOK * NTOK];    // per-head logits (fp16)
__device__ float  g_Wf[(size_t)NTOK * NTOK];            // fused weights
__device__ double g_stats[2];

// ---------------- helpers ----------------
__device__ __forceinline__ float warp_max(float v) {
    #pragma unroll
    for (int o = 16; o; o >>= 1) v = fmaxf(v, __shfl_xor_sync(0xffffffffu, v, o));
    return v;
}
__device__ __forceinline__ float warp_sum(float v) {
    #pragma unroll
    for (int o = 16; o; o >>= 1) v += __shfl_xor_sync(0xffffffffu, v, o);
    return v;
}
__device__ __forceinline__ void mma_tf32(float* d, const uint32_t* a, const uint32_t* b) {
    asm volatile(
        "mma.sync.aligned.m16n8k8.row.col.f32.tf32.tf32.f32 "
        "{%0,%1,%2,%3}, {%4,%5,%6,%7}, {%8,%9}, {%0,%1,%2,%3};\n"
        : "+f"(d[0]), "+f"(d[1]), "+f"(d[2]), "+f"(d[3])
        : "r"(a[0]), "r"(a[1]), "r"(a[2]), "r"(a[3]), "r"(b[0]), "r"(b[1]));
}
__device__ __forceinline__ void cpa16(uint32_t smem, const void* gptr) {
    asm volatile("cp.async.ca.shared.global [%0], [%1], 16;\n" :: "r"(smem), "l"(gptr));
}
#define CP_COMMIT()  asm volatile("cp.async.commit_group;\n")
#define CP_WAIT(N)   asm volatile("cp.async.wait_group %0;\n" :: "n"(N))

#define ASTR 20    // smem stride for [row][k16] tiles: conflict-free fragment LDS
#define BSTR 136   // smem stride for [k16][col128] tiles (NN B)

// ---------------- tf32 TC NT GEMM: C = scale*A.B^T (+bias), batched, OutT output ----------------
template <typename OutT>
__global__ __launch_bounds__(256, 2) void gemm_nt_tc(
    const float* __restrict__ A, int lda, long long strideA,
    const float* __restrict__ B, int ldb, long long strideB,
    OutT* __restrict__ C, int ldc, long long strideC,
    int K, const float* __restrict__ bias, float scale)
{
    __shared__ float As[2][128 * ASTR];
    __shared__ float Bs[2][128 * ASTR];

    const int z = blockIdx.z;
    A += (size_t)z * strideA;
    B += (size_t)z * strideB;
    C += (size_t)z * strideC;

    const int tid = threadIdx.x;
    const int row0 = blockIdx.y * 128, col0 = blockIdx.x * 128;
    const int wid = tid >> 5, lane = tid & 31;
    const int wm = wid & 3, wn = wid >> 2;   // 4 x 2 warp grid
    const int g = lane >> 2, tig = lane & 3;

    float acc[2][8][4];
    #pragma unroll
    for (int i = 0; i < 2; i++)
        #pragma unroll
        for (int j = 0; j < 8; j++)
            #pragma unroll
            for (int q = 0; q < 4; q++) acc[i][j][q] = 0.f;

    const int c0 = tid * 2;
    const int cr0 = c0 >> 2, cs0 = (c0 & 3) * 4;
    const int cr1 = (c0 + 1) >> 2, cs1 = ((c0 + 1) & 3) * 4;

    const uint32_t sA = (uint32_t)__cvta_generic_to_shared(&As[0][0]);
    const uint32_t sB = (uint32_t)__cvta_generic_to_shared(&Bs[0][0]);
    const uint32_t stg = 128 * ASTR * 4;

    const float* gA0 = A + (size_t)(row0 + cr0) * lda + cs0;
    const float* gA1 = A + (size_t)(row0 + cr1) * lda + cs1;
    const float* gB0 = B + (size_t)(col0 + cr0) * ldb + cs0;
    const float* gB1 = B + (size_t)(col0 + cr1) * ldb + cs1;
    const uint32_t dA0 = sA + (cr0 * ASTR + cs0) * 4;
    const uint32_t dA1 = sA + (cr1 * ASTR + cs1) * 4;
    const uint32_t dB0 = sB + (cr0 * ASTR + cs0) * 4;
    const uint32_t dB1 = sB + (cr1 * ASTR + cs1) * 4;

    const int niter = K >> 4;

    cpa16(dA0, gA0); cpa16(dA1, gA1);
    cpa16(dB0, gB0); cpa16(dB1, gB1);
    CP_COMMIT();

    for (int it = 0; it < niter; ++it) {
        if (it + 1 < niter) {
            const int st = (it + 1) & 1;
            const int k0 = (it + 1) << 4;
            cpa16(dA0 + st * stg, gA0 + k0); cpa16(dA1 + st * stg, gA1 + k0);
            cpa16(dB0 + st * stg, gB0 + k0); cpa16(dB1 + st * stg, gB1 + k0);
            CP_COMMIT();
            CP_WAIT(1);
        } else {
            CP_WAIT(0);
        }
        __syncthreads();

        const float* as = As[it & 1];
        const float* bs = Bs[it & 1];
        #pragma unroll
        for (int kk = 0; kk < 16; kk += 8) {
            uint32_t af[2][4];
            #pragma unroll
            for (int mi = 0; mi < 2; mi++) {
                int rb = wm * 32 + mi * 16;
                af[mi][0] = __float_as_uint(as[(rb + g    ) * ASTR + kk + tig    ]);
                af[mi][1] = __float_as_uint(as[(rb + g + 8) * ASTR + kk + tig    ]);
                af[mi][2] = __float_as_uint(as[(rb + g    ) * ASTR + kk + tig + 4]);
                af[mi][3] = __float_as_uint(as[(rb + g + 8) * ASTR + kk + tig + 4]);
            }
            #pragma unroll
            for (int ni = 0; ni < 8; ni++) {
                int cb = wn * 64 + ni * 8;
                uint32_t bf[2];
                bf[0] = __float_as_uint(bs[(cb + g) * ASTR + kk + tig    ]);
                bf[1] = __float_as_uint(bs[(cb + g) * ASTR + kk + tig + 4]);
                #pragma unroll
                for (int mi = 0; mi < 2; mi++) mma_tf32(acc[mi][ni], af[mi], bf);
            }
        }
        __syncthreads();
    }

    #pragma unroll
    for (int mi = 0; mi < 2; mi++) {
        #pragma unroll
        for (int gg = 0; gg < 2; gg++) {
            int r = row0 + wm * 32 + mi * 16 + g + gg * 8;
            #pragma unroll
            for (int ni = 0; ni < 8; ni++) {
                int c = col0 + wn * 64 + ni * 8 + tig * 2;
                float vx = acc[mi][ni][gg * 2 + 0] * scale;
                float vy = acc[mi][ni][gg * 2 + 1] * scale;
                if (bias) { vx += bias[c]; vy += bias[c + 1]; }
                if constexpr (sizeof(OutT) == 2) {
                    *(__half2*)((__half*)C + (size_t)r * ldc + c) = __floats2half2_rn(vx, vy);
                } else {
                    float2 v; v.x = vx; v.y = vy;
                    *(float2*)((float*)C + (size_t)r * ldc + c) = v;
                }
            }
        }
    }
}

// ---------------- tf32 TC NN GEMM: C = A @ B, 64x128 tiles (2 CTAs/SM) ----------------
__global__ __launch_bounds__(256, 2) void gemm_nn_tc(
    const float* __restrict__ A, int lda,
    const float* __restrict__ B, int ldb,
    float* __restrict__ C, int ldc, int K)
{
    __shared__ float As[2][64 * ASTR];
    __shared__ float Bs[2][16 * BSTR];

    const int tid = threadIdx.x;
    const int row0 = blockIdx.y * 64, col0 = blockIdx.x * 128;
    const int wid = tid >> 5, lane = tid & 31;
    const int wm = wid & 1, wn = wid >> 1;   // 2 x 4 warp grid
    const int g = lane >> 2, tig = lane & 3;

    float acc[2][4][4];
    #pragma unroll
    for (int i = 0; i < 2; i++)
        #pragma unroll
        for (int j = 0; j < 4; j++)
            #pragma unroll
            for (int q = 0; q < 4; q++) acc[i][j][q] = 0.f;

    // A: 64x16 = 256 16B-chunks, 1/thread.  B: 16x128 = 512 chunks, 2/thread.
    const int ar = tid >> 2, as_ = (tid & 3) * 4;
    const int b0 = tid * 2;
    const int bk0 = b0 >> 5, bs0 = (b0 & 31) * 4;
    const int bk1 = (b0 + 1) >> 5, bs1 = ((b0 + 1) & 31) * 4;

    const uint32_t sA = (uint32_t)__cvta_generic_to_shared(&As[0][0]);
    const uint32_t sB = (uint32_t)__cvta_generic_to_shared(&Bs[0][0]);
    const uint32_t stgA = 64 * ASTR * 4;
    const uint32_t stgB = 16 * BSTR * 4;

    const float* gA0 = A + (size_t)(row0 + ar) * lda + as_;
    const float* gB0 = B + (size_t)bk0 * ldb + col0 + bs0;
    const float* gB1 = B + (size_t)bk1 * ldb + col0 + bs1;
    const uint32_t dA0 = sA + (ar * ASTR + as_) * 4;
    const uint32_t dB0 = sB + (bk0 * BSTR + bs0) * 4;
    const uint32_t dB1 = sB + (bk1 * BSTR + bs1) * 4;

    const int niter = K >> 4;

    cpa16(dA0, gA0);
    cpa16(dB0, gB0); cpa16(dB1, gB1);
    CP_COMMIT();

    for (int it = 0; it < niter; ++it) {
        if (it + 1 < niter) {
            const int st = (it + 1) & 1;
            const long long k0 = (long long)(it + 1) << 4;
            cpa16(dA0 + st * stgA, gA0 + k0);
            cpa16(dB0 + st * stgB, gB0 + k0 * ldb);
            cpa16(dB1 + st * stgB, gB1 + k0 * ldb);
            CP_COMMIT();
            CP_WAIT(1);
        } else {
            CP_WAIT(0);
        }
        __syncthreads();

        const float* as = As[it & 1];
        const float* bs = Bs[it & 1];
        #pragma unroll
        for (int kk = 0; kk < 16; kk += 8) {
            uint32_t af[2][4];
            #pragma unroll
            for (int mi = 0; mi < 2; mi++) {
                int rb = wm * 32 + mi * 16;
                af[mi][0] = __float_as_uint(as[(rb + g    ) * ASTR + kk + tig    ]);
                af[mi][1] = __float_as_uint(as[(rb + g + 8) * ASTR + kk + tig    ]);
                af[mi][2] = __float_as_uint(as[(rb + g    ) * ASTR + kk + tig + 4]);
                af[mi][3] = __float_as_uint(as[(rb + g + 8) * ASTR + kk + tig + 4]);
            }
            #pragma unroll
            for (int ni = 0; ni < 4; ni++) {
                int cb = wn * 32 + ni * 8;
                uint32_t bf[2];
                bf[0] = __float_as_uint(bs[(kk + tig    ) * BSTR + cb + g]);
                bf[1] = __float_as_uint(bs[(kk + tig + 4) * BSTR + cb + g]);
                #pragma unroll
                for (int mi = 0; mi < 2; mi++) mma_tf32(acc[mi][ni], af[mi], bf);
            }
        }
        __syncthreads();
    }

    #pragma unroll
    for (int mi = 0; mi < 2; mi++) {
        #pragma unroll
        for (int gg = 0; gg < 2; gg++) {
            int r = row0 + wm * 32 + mi * 16 + g + gg * 8;
            #pragma unroll
            for (int ni = 0; ni < 4; ni++) {
                int c = col0 + wn * 32 + ni * 8 + tig * 2;
                float2 v;
                v.x = acc[mi][ni][gg * 2 + 0];
                v.y = acc[mi][ni][gg * 2 + 1];
                *(float2*)(C + (size_t)r * ldc + c) = v;
            }
        }
    }
}

// ---------------- fused: 12-head softmax avg (no max-shift) + Gaussian + stats ----------------
__global__ void zero_stats_kernel() { g_stats[0] = 0.0; g_stats[1] = 0.0; }

extern __shared__ __half sh_exp[];  // NHEAD * NTOK halves (73728 B)

#define HT 256
__global__ __launch_bounds__(HT) void headsmax_wf_kernel(const float* __restrict__ dd)
{
    __shared__ float redA[8], redB[8];
    __shared__ float invZ[NHEAD];
    const int i = blockIdx.x, tid = threadIdx.x;
    const int lane = tid & 31, wid = tid >> 5;
    __half2* shx = (__half2*)sh_exp;
    const int NP = NTOK / 2;

    // per head: exp (no shift: |logit| <~ 2) + sum; stage exp in fp16 smem
    #pragma unroll
    for (int h = 0; h < NHEAD; h++) {
        const __half2* row = (const __half2*)(g_Sh + (size_t)h * NTOK * NTOK + (size_t)i * NTOK);
        float lsum = 0.f;
        for (int j = tid; j < NP; j += HT) {
            float2 v = __half22float2(row[j]);
            float e0 = __expf(v.x), e1 = __expf(v.y);
            shx[h * NP + j] = __floats2half2_rn(e0, e1);
            lsum += e0 + e1;
        }
        lsum = warp_sum(lsum);
        if (lane == 0) redB[wid] = lsum;
        __syncthreads();
        if (wid == 0) {
            float t = (lane < 8) ? redB[lane] : 0.f;
            t = warp_sum(t);
            if (lane == 0) invZ[h] = 1.f / (t * (float)NHEAD);
        }
        __syncthreads();
    }

    float iz[NHEAD];
    #pragma unroll
    for (int h = 0; h < NHEAD; h++) iz[h] = invZ[h];

    const float2* drow = (const float2*)(dd + (size_t)i * NTOK);
    float2* frow = (float2*)(g_Wf + (size_t)i * NTOK);
    float s1 = 0.f, s2 = 0.f;
    for (int j = tid; j < NP; j += HT) {
        float wa0 = 0.f, wa1 = 0.f;
        #pragma unroll
        for (int h = 0; h < NHEAD; h++) {
            float2 e = __half22float2(shx[h * NP + j]);
            wa0 += e.x * iz[h];
            wa1 += e.y * iz[h];
        }
        float2 d = drow[j];
        float wf0 = __expf(-0.5f * d.x * d.x) * wa0;
        float wf1 = __expf(-0.5f * d.y * d.y) * wa1;
        float2 w; w.x = wf0; w.y = wf1;
        frow[j] = w;
        s1 += wf0 + wf1;
        s2 += wf0 * wf0 + wf1 * wf1;
    }
    s1 = warp_sum(s1);
    s2 = warp_sum(s2);
    if (lane == 0) { redA[wid] = s1; redB[wid] = s2; }
    __syncthreads();
    if (wid == 0) {
        float a = (lane < 8) ? redA[lane] : 0.f;
        float b = (lane < 8) ? redB[lane] : 0.f;
        a = warp_sum(a);
        b = warp_sum(b);
        if (lane == 0) {
            atomicAdd(&g_stats[0], (double)a);
            atomicAdd(&g_stats[1], (double)b);
        }
    }
}

// ---------------- guided attention masked softmax (in place on g_S) ----------------
__global__ __launch_bounds__(256) void masked_softmax_kernel()
{
    __shared__ float z[NTOK];
    __shared__ float redA[8], redB[8];
    __shared__ float sh_thr;
    const int i = blockIdx.x, tid = threadIdx.x;
    const int lane = tid & 31, wid = tid >> 5;

    if (tid == 0) {
        double cnt = (double)NTOK * (double)NTOK;
        double mean = g_stats[0] / cnt;
        double var = (g_stats[1] - g_stats[0] * g_stats[0] / cnt) / (cnt - 1.0);
        if (var < 0.0) var = 0.0;
        sh_thr = (float)(mean + 0.5 * sqrt(var));
    }
    __syncthreads();
    const float thr = sh_thr;
    const float invthr = 1.f / thr;

    float* srow = g_S + (size_t)i * NTOK;
    const float* frow = g_Wf + (size_t)i * NTOK;

    float lmax = -1e30f;
    for (int j = tid; j < NTOK; j += 256) {
        float wf = frow[j];
        float ww = (wf < thr) ? wf * invthr : 1.f;
        float v = srow[j] * ww;
        z[j] = v;
        lmax = fmaxf(lmax, v);
    }
    lmax = warp_max(lmax);
    if (lane == 0) redA[wid] = lmax;
    __syncthreads();
    if (wid == 0) {
        float t = (lane < 8) ? redA[lane] : -1e30f;
        t = warp_max(t);
        if (lane == 0) redA[0] = t;
    }
    __syncthreads();
    const float m = redA[0];

    float lsum = 0.f;
    for (int j = tid; j < NTOK; j += 256) {
        float e = __expf(z[j] - m);
        z[j] = e;
        lsum += e;
    }
    lsum = warp_sum(lsum);
    if (lane == 0) redB[wid] = lsum;
    __syncthreads();
    if (wid == 0) {
        float t = (lane < 8) ? redB[lane] : 0.f;
        t = warp_sum(t);
        if (lane == 0) redB[0] = t;
    }
    __syncthreads();
    const float invs = 1.f / redB[0];

    for (int j = tid; j < NTOK; j += 256)
        srow[j] = z[j] * invs;
}

// ---------------- residual + LayerNorm ----------------
__global__ __launch_bounds__(256) void ln_kernel(
    const float* __restrict__ hs,
    const float* __restrict__ gamma,
    const float* __restrict__ beta,
    float* __restrict__ out)
{
    const int i = blockIdx.x, tid = threadIdx.x;
    const int lane = tid & 31, wid = tid >> 5;
    __shared__ float r1[8], r2[8];

    const float* orow = g_O + (size_t)i * DIM;
    const float* srow = hs + (size_t)i * DIM;

    float x[3];
    float s = 0.f, ss = 0.f;
    #pragma unroll
    for (int t = 0; t < 3; t++) {
        int c = tid + t * 256;
        x[t] = srow[c] + orow[c];
        s += x[t];
        ss += x[t] * x[t];
    }
    s = warp_sum(s);
    ss = warp_sum(ss);
    if (lane == 0) { r1[wid] = s; r2[wid] = ss; }
    __syncthreads();
    if (wid == 0) {
        float a = (lane < 8) ? r1[lane] : 0.f;
        float b = (lane < 8) ? r2[lane] : 0.f;
        a = warp_sum(a);
        b = warp_sum(b);
        if (lane == 0) { r1[0] = a; r2[0] = b; }
    }
    __syncthreads();
    const float mu = r1[0] * (1.f / DIM);
    const float var = r2[0] * (1.f / DIM) - mu * mu;
    const float inv = rsqrtf(var + 1e-5f);

    #pragma unroll
    for (int t = 0; t < 3; t++) {
        int c = tid + t * 256;
        out[(size_t)i * DIM + c] = (x[t] - mu) * inv * gamma[c] + beta[c];
    }
}

// ---------------- host ----------------
extern "C" void kernel_launch(void* const* d_in, const int* in_sizes, int n_in,
                              void* d_out, int out_size)
{
    const float* h_a  = (const float*)d_in[0];
    const float* h_s  = (const float*)d_in[1];
    const float* dep  = (const float*)d_in[2];
    const float* Wq_a = (const float*)d_in[3];
    const float* bq_a = (const float*)d_in[4];
    const float* Wk_a = (const float*)d_in[5];
    const float* bk_a = (const float*)d_in[6];
    const float* Wq   = (const float*)d_in[7];
    const float* bq   = (const float*)d_in[8];
    const float* Wk   = (const float*)d_in[9];
    const float* bk   = (const float*)d_in[10];
    const float* Wv   = (const float*)d_in[11];
    const float* bv   = (const float*)d_in[12];
    const float* lng  = (const float*)d_in[13];
    const float* lnb  = (const float*)d_in[14];
    float* out = (float*)d_out;

    float *qa, *ka, *Q, *K, *V, *O, *S;
    __half* Sh;
    cudaGetSymbolAddress((void**)&qa, g_qa);
    cudaGetSymbolAddress((void**)&ka, g_ka);
    cudaGetSymbolAddress((void**)&Q,  g_Q);
    cudaGetSymbolAddress((void**)&K,  g_K);
    cudaGetSymbolAddress((void**)&V,  g_V);
    cudaGetSymbolAddress((void**)&O,  g_O);
    cudaGetSymbolAddress((void**)&S,  g_S);
    cudaGetSymbolAddress((void**)&Sh, g_Sh);

    static cudaStream_t s1;
    static cudaEvent_t e0, e1;
    static int inited = 0;
    if (!inited) {
        cudaStreamCreateWithFlags(&s1, cudaStreamNonBlocking);
        cudaEventCreateWithFlags(&e0, cudaEventDisableTiming);
        cudaEventCreateWithFlags(&e1, cudaEventDisableTiming);
        cudaFuncSetAttribute(headsmax_wf_kernel,
                             cudaFuncAttributeMaxDynamicSharedMemorySize,
                             NHEAD * NTOK * (int)sizeof(__half));
        inited = 1;
    }

    const dim3 blk(256);
    const dim3 gProj(DIM / 128, NTOK / 128);          // 6 x 24
    const dim3 gNN(NTOK / 128, NTOK / 128);           // 24 x 24
    const dim3 gHeads(NTOK / 128, NTOK / 128, NHEAD); // 24 x 24 x 12
    const dim3 gAV(DIM / 128, NTOK / 64);             // 6 x 48

    // fork side stream from capture (legacy) stream
    cudaEventRecord(e0, 0);
    cudaStreamWaitEvent(s1, e0, 0);

    // ---- chain A (s1): structural-attention weights ----
    gemm_nt_tc<float><<<gProj, blk, 0, s1>>>(h_a, DIM, 0, Wq_a, DIM, 0, qa, DIM, 0, DIM, bq_a, 1.f);
    gemm_nt_tc<float><<<gProj, blk, 0, s1>>>(h_a, DIM, 0, Wk_a, DIM, 0, ka, DIM, 0, DIM, bk_a, 1.f);
    gemm_nt_tc<__half><<<gHeads, blk, 0, s1>>>(qa, DIM, HDIM, ka, DIM, HDIM,
                                               Sh, NTOK, (long long)NTOK * NTOK,
                                               HDIM, nullptr, 0.125f);
    zero_stats_kernel<<<1, 1, 0, s1>>>();
    headsmax_wf_kernel<<<NTOK, HT, NHEAD * NTOK * sizeof(__half), s1>>>(dep);
    cudaEventRecord(e1, s1);

    // ---- chain B (legacy stream): guided attention ----
    gemm_nt_tc<float><<<gProj, blk>>>(h_s, DIM, 0, Wq, DIM, 0, Q, DIM, 0, DIM, bq, 1.f);
    gemm_nt_tc<float><<<gProj, blk>>>(h_s, DIM, 0, Wk, DIM, 0, K, DIM, 0, DIM, bk, 1.f);
    gemm_nt_tc<float><<<gProj, blk>>>(h_s, DIM, 0, Wv, DIM, 0, V, DIM, 0, DIM, bv, 1.f);
    const float score_scale = 1.f / sqrtf((float)DIM);
    gemm_nt_tc<float><<<gNN, blk>>>(Q, DIM, 0, K, DIM, 0, S, NTOK, 0, DIM, nullptr, score_scale);

    // join: masked softmax needs Wf + stats from chain A
    cudaStreamWaitEvent(0, e1, 0);
    masked_softmax_kernel<<<NTOK, 256>>>();
    gemm_nn_tc<<<gAV, blk>>>(S, NTOK, V, DIM, O, DIM, NTOK);
    ln_kernel<<<NTOK, 256>>>(h_s, lng, lnb, out);
}

// round 5
// speedup vs baseline: 2.8049x; 1.6687x over previous
#include <cuda_runtime.h>
#include <cuda_fp16.h>
#include <cuda_bf16.h>
#include <math.h>
#include <stdint.h>

#define NTOK 3072
#define DIM  768
#define NHEAD 12
#define HDIM 64

// ---------------- static device scratch (raw types to avoid ctor issues) ----------------
__device__ float g_qa[NTOK * DIM];
__device__ float g_ka[NTOK * DIM];
__device__ unsigned short g_Qb[NTOK * DIM];                // bf16
__device__ unsigned short g_Kb[NTOK * DIM];                // bf16
__device__ float g_V [NTOK * DIM];
__device__ unsigned short g_Vt[DIM * NTOK];                // bf16, transposed V
__device__ float g_O [NTOK * DIM];
__device__ float g_S [(size_t)NTOK * NTOK];                // fp32 scores
__device__ unsigned short g_Att[(size_t)NTOK * NTOK];      // bf16 attn
__device__ unsigned short g_Shx[(size_t)NHEAD * NTOK * NTOK]; // fp16 exp(logit) planes
__device__ float g_Wf[(size_t)NTOK * NTOK];
__device__ double g_stats[2];

// ---------------- helpers ----------------
__device__ __forceinline__ float warp_sum(float v) {
    #pragma unroll
    for (int o = 16; o; o >>= 1) v += __shfl_xor_sync(0xffffffffu, v, o);
    return v;
}
__device__ __forceinline__ void mma_tf32(float* d, const uint32_t* a, const uint32_t* b) {
    asm volatile(
        "mma.sync.aligned.m16n8k8.row.col.f32.tf32.tf32.f32 "
        "{%0,%1,%2,%3}, {%4,%5,%6,%7}, {%8,%9}, {%0,%1,%2,%3};\n"
        : "+f"(d[0]), "+f"(d[1]), "+f"(d[2]), "+f"(d[3])
        : "r"(a[0]), "r"(a[1]), "r"(a[2]), "r"(a[3]), "r"(b[0]), "r"(b[1]));
}
__device__ __forceinline__ void mma_bf16(float* d, const uint32_t* a, const uint32_t* b) {
    asm volatile(
        "mma.sync.aligned.m16n8k16.row.col.f32.bf16.bf16.f32 "
        "{%0,%1,%2,%3}, {%4,%5,%6,%7}, {%8,%9}, {%0,%1,%2,%3};\n"
        : "+f"(d[0]), "+f"(d[1]), "+f"(d[2]), "+f"(d[3])
        : "r"(a[0]), "r"(a[1]), "r"(a[2]), "r"(a[3]), "r"(b[0]), "r"(b[1]));
}
__device__ __forceinline__ void cpa16(uint32_t smem, const void* gptr) {
    asm volatile("cp.async.ca.shared.global [%0], [%1], 16;\n" :: "r"(smem), "l"(gptr));
}
#define CP_COMMIT()  asm volatile("cp.async.commit_group;\n")
#define CP_WAIT(N)   asm volatile("cp.async.wait_group %0;\n" :: "n"(N))

#define ASTR 20    // fp32 tile row stride (floats): conflict-free fragment LDS
#define HSTR 20    // bf16 tile row stride (b32 units): 16 data b32 + 4 pad, conflict-free

// ================= tf32 TC NT GEMM (projections): C = scale*A.B^T + bias =================
template <typename OutT>
__global__ __launch_bounds__(256, 2) void gemm_nt_tc(
    const float* __restrict__ A, int lda,
    const float* __restrict__ B, int ldb,
    OutT* __restrict__ C, int ldc,
    int K, const float* __restrict__ bias, float scale)
{
    __shared__ float As[2][128 * ASTR];
    __shared__ float Bs[2][128 * ASTR];

    const int tid = threadIdx.x;
    const int row0 = blockIdx.y * 128, col0 = blockIdx.x * 128;
    const int wid = tid >> 5, lane = tid & 31;
    const int wm = wid & 3, wn = wid >> 2;
    const int g = lane >> 2, tig = lane & 3;

    float acc[2][8][4];
    #pragma unroll
    for (int i = 0; i < 2; i++)
        #pragma unroll
        for (int j = 0; j < 8; j++)
            #pragma unroll
            for (int q = 0; q < 4; q++) acc[i][j][q] = 0.f;

    const int c0 = tid * 2;
    const int cr0 = c0 >> 2, cs0 = (c0 & 3) * 4;
    const int cr1 = (c0 + 1) >> 2, cs1 = ((c0 + 1) & 3) * 4;

    const uint32_t sA = (uint32_t)__cvta_generic_to_shared(&As[0][0]);
    const uint32_t sB = (uint32_t)__cvta_generic_to_shared(&Bs[0][0]);
    const uint32_t stg = 128 * ASTR * 4;

    const float* gA0 = A + (size_t)(row0 + cr0) * lda + cs0;
    const float* gA1 = A + (size_t)(row0 + cr1) * lda + cs1;
    const float* gB0 = B + (size_t)(col0 + cr0) * ldb + cs0;
    const float* gB1 = B + (size_t)(col0 + cr1) * ldb + cs1;
    const uint32_t dA0 = sA + (cr0 * ASTR + cs0) * 4;
    const uint32_t dA1 = sA + (cr1 * ASTR + cs1) * 4;
    const uint32_t dB0 = sB + (cr0 * ASTR + cs0) * 4;
    const uint32_t dB1 = sB + (cr1 * ASTR + cs1) * 4;

    const int niter = K >> 4;

    cpa16(dA0, gA0); cpa16(dA1, gA1);
    cpa16(dB0, gB0); cpa16(dB1, gB1);
    CP_COMMIT();

    for (int it = 0; it < niter; ++it) {
        if (it + 1 < niter) {
            const int st = (it + 1) & 1;
            const int k0 = (it + 1) << 4;
            cpa16(dA0 + st * stg, gA0 + k0); cpa16(dA1 + st * stg, gA1 + k0);
            cpa16(dB0 + st * stg, gB0 + k0); cpa16(dB1 + st * stg, gB1 + k0);
            CP_COMMIT();
            CP_WAIT(1);
        } else {
            CP_WAIT(0);
        }
        __syncthreads();

        const float* as = As[it & 1];
        const float* bs = Bs[it & 1];
        #pragma unroll
        for (int kk = 0; kk < 16; kk += 8) {
            uint32_t af[2][4];
            #pragma unroll
            for (int mi = 0; mi < 2; mi++) {
                int rb = wm * 32 + mi * 16;
                af[mi][0] = __float_as_uint(as[(rb + g    ) * ASTR + kk + tig    ]);
                af[mi][1] = __float_as_uint(as[(rb + g + 8) * ASTR + kk + tig    ]);
                af[mi][2] = __float_as_uint(as[(rb + g    ) * ASTR + kk + tig + 4]);
                af[mi][3] = __float_as_uint(as[(rb + g + 8) * ASTR + kk + tig + 4]);
            }
            #pragma unroll
            for (int ni = 0; ni < 8; ni++) {
                int cb = wn * 64 + ni * 8;
                uint32_t bf[2];
                bf[0] = __float_as_uint(bs[(cb + g) * ASTR + kk + tig    ]);
                bf[1] = __float_as_uint(bs[(cb + g) * ASTR + kk + tig + 4]);
                #pragma unroll
                for (int mi = 0; mi < 2; mi++) mma_tf32(acc[mi][ni], af[mi], bf);
            }
        }
        __syncthreads();
    }

    #pragma unroll
    for (int mi = 0; mi < 2; mi++) {
        #pragma unroll
        for (int gg = 0; gg < 2; gg++) {
            int r = row0 + wm * 32 + mi * 16 + g + gg * 8;
            #pragma unroll
            for (int ni = 0; ni < 8; ni++) {
                int c = col0 + wn * 64 + ni * 8 + tig * 2;
                float vx = acc[mi][ni][gg * 2 + 0] * scale;
                float vy = acc[mi][ni][gg * 2 + 1] * scale;
                if (bias) { vx += bias[c]; vy += bias[c + 1]; }
                if constexpr (sizeof(OutT) == 2) {
                    __nv_bfloat162 bv = __float22bfloat162_rn(make_float2(vx, vy));
                    *(__nv_bfloat162*)((__nv_bfloat16*)C + (size_t)r * ldc + c) = bv;
                } else {
                    float2 v; v.x = vx; v.y = vy;
                    *(float2*)((float*)C + (size_t)r * ldc + c) = v;
                }
            }
        }
    }
}

// ================= fused 12-head logits GEMM + exp epilogue (tf32) =================
__global__ __launch_bounds__(256, 2) void heads_gemm(
    const float* __restrict__ A,   // qa [3072 x 768]
    const float* __restrict__ B,   // ka [3072 x 768]
    unsigned short* __restrict__ P)  // 12 fp16 exp planes
{
    __shared__ float As[2][128 * ASTR];
    __shared__ float Bs[2][128 * ASTR];

    const int tid = threadIdx.x;
    const int row0 = blockIdx.y * 128, col0 = blockIdx.x * 128;
    const int wid = tid >> 5, lane = tid & 31;
    const int wm = wid & 3, wn = wid >> 2;
    const int g = lane >> 2, tig = lane & 3;

    const int c0 = tid * 2;
    const int cr0 = c0 >> 2, cs0 = (c0 & 3) * 4;
    const int cr1 = (c0 + 1) >> 2, cs1 = ((c0 + 1) & 3) * 4;

    const uint32_t sA = (uint32_t)__cvta_generic_to_shared(&As[0][0]);
    const uint32_t sB = (uint32_t)__cvta_generic_to_shared(&Bs[0][0]);
    const uint32_t stg = 128 * ASTR * 4;

    const float* gA0 = A + (size_t)(row0 + cr0) * DIM + cs0;
    const float* gA1 = A + (size_t)(row0 + cr1) * DIM + cs1;
    const float* gB0 = B + (size_t)(col0 + cr0) * DIM + cs0;
    const float* gB1 = B + (size_t)(col0 + cr1) * DIM + cs1;
    const uint32_t dA0 = sA + (cr0 * ASTR + cs0) * 4;
    const uint32_t dA1 = sA + (cr1 * ASTR + cs1) * 4;
    const uint32_t dB0 = sB + (cr0 * ASTR + cs0) * 4;
    const uint32_t dB1 = sB + (cr1 * ASTR + cs1) * 4;

    const int niter = DIM >> 4;  // 48

    cpa16(dA0, gA0); cpa16(dA1, gA1);
    cpa16(dB0, gB0); cpa16(dB1, gB1);
    CP_COMMIT();

    for (int h = 0; h < NHEAD; h++) {
        float acc[2][8][4];
        #pragma unroll
        for (int i = 0; i < 2; i++)
            #pragma unroll
            for (int j = 0; j < 8; j++)
                #pragma unroll
                for (int q = 0; q < 4; q++) acc[i][j][q] = 0.f;

        #pragma unroll
        for (int ki = 0; ki < 4; ki++) {
            const int it = h * 4 + ki;
            if (it + 1 < niter) {
                const int st = (it + 1) & 1;
                const int k0 = (it + 1) << 4;
                cpa16(dA0 + st * stg, gA0 + k0); cpa16(dA1 + st * stg, gA1 + k0);
                cpa16(dB0 + st * stg, gB0 + k0); cpa16(dB1 + st * stg, gB1 + k0);
                CP_COMMIT();
                CP_WAIT(1);
            } else {
                CP_WAIT(0);
            }
            __syncthreads();

            const float* as = As[it & 1];
            const float* bs = Bs[it & 1];
            #pragma unroll
            for (int kk = 0; kk < 16; kk += 8) {
                uint32_t af[2][4];
                #pragma unroll
                for (int mi = 0; mi < 2; mi++) {
                    int rb = wm * 32 + mi * 16;
                    af[mi][0] = __float_as_uint(as[(rb + g    ) * ASTR + kk + tig    ]);
                    af[mi][1] = __float_as_uint(as[(rb + g + 8) * ASTR + kk + tig    ]);
                    af[mi][2] = __float_as_uint(as[(rb + g    ) * ASTR + kk + tig + 4]);
                    af[mi][3] = __float_as_uint(as[(rb + g + 8) * ASTR + kk + tig + 4]);
                }
                #pragma unroll
                for (int ni = 0; ni < 8; ni++) {
                    int cb = wn * 64 + ni * 8;
                    uint32_t bf[2];
                    bf[0] = __float_as_uint(bs[(cb + g) * ASTR + kk + tig    ]);
                    bf[1] = __float_as_uint(bs[(cb + g) * ASTR + kk + tig + 4]);
                    #pragma unroll
                    for (int mi = 0; mi < 2; mi++) mma_tf32(acc[mi][ni], af[mi], bf);
                }
            }
            __syncthreads();
        }

        // epilogue: store exp(logit/8) as fp16 into plane h
        __half* plane = (__half*)P + (size_t)h * NTOK * NTOK;
        #pragma unroll
        for (int mi = 0; mi < 2; mi++) {
            #pragma unroll
            for (int gg = 0; gg < 2; gg++) {
                int r = row0 + wm * 32 + mi * 16 + g + gg * 8;
                #pragma unroll
                for (int ni = 0; ni < 8; ni++) {
                    int c = col0 + wn * 64 + ni * 8 + tig * 2;
                    float e0 = __expf(0.125f * acc[mi][ni][gg * 2 + 0]);
                    float e1 = __expf(0.125f * acc[mi][ni][gg * 2 + 1]);
                    *(__half2*)(plane + (size_t)r * NTOK + c) = __floats2half2_rn(e0, e1);
                }
            }
        }
    }
}

// ================= bf16 TC NT GEMM: C = scale * A.B^T (fp32 out) =================
template <int BM>
__global__ __launch_bounds__(256, 2) void gemm_nt_bf(
    const unsigned short* __restrict__ A, int lda,
    const unsigned short* __restrict__ B, int ldb,
    float* __restrict__ C, int ldc, int K, float scale)
{
    constexpr int WMN = BM / 32;       // warps along M (4 or 2)
    constexpr int WNN = 8 / WMN;       // warps along N (2 or 4)
    constexpr int NI  = 128 / (WNN * 8);  // 8 or 4
    constexpr int NA  = BM * 4 / 256;  // A chunks per thread (2 or 1)

    __shared__ uint32_t As[2][BM * HSTR];
    __shared__ uint32_t Bs[2][128 * HSTR];

    const int tid = threadIdx.x;
    const int row0 = blockIdx.y * BM, col0 = blockIdx.x * 128;
    const int wid = tid >> 5, lane = tid & 31;
    const int wm = wid % WMN, wn = wid / WMN;
    const int g = lane >> 2, tig = lane & 3;

    float acc[2][NI][4];
    #pragma unroll
    for (int i = 0; i < 2; i++)
        #pragma unroll
        for (int j = 0; j < NI; j++)
            #pragma unroll
            for (int q = 0; q < 4; q++) acc[i][j][q] = 0.f;

    const uint32_t sA = (uint32_t)__cvta_generic_to_shared(&As[0][0]);
    const uint32_t sB = (uint32_t)__cvta_generic_to_shared(&Bs[0][0]);
    const uint32_t stgA = BM * HSTR * 4;
    const uint32_t stgB = 128 * HSTR * 4;

    // A: BM rows x 32 halves = BM*4 chunks; B: 128 rows x 4 chunks = 512
    const unsigned short* gA[NA];
    uint32_t dA[NA];
    #pragma unroll
    for (int t = 0; t < NA; t++) {
        int ch = tid + t * 256;
        int cr = ch >> 2, cc = ch & 3;
        gA[t] = A + (size_t)(row0 + cr) * lda + cc * 8;
        dA[t] = sA + (cr * HSTR + cc * 4) * 4;
    }
    const unsigned short* gB[2];
    uint32_t dB[2];
    #pragma unroll
    for (int t = 0; t < 2; t++) {
        int ch = tid + t * 256;
        int cr = ch >> 2, cc = ch & 3;
        gB[t] = B + (size_t)(col0 + cr) * ldb + cc * 8;
        dB[t] = sB + (cr * HSTR + cc * 4) * 4;
    }

    const int niter = K >> 5;  // BK = 32 halves

    #pragma unroll
    for (int t = 0; t < NA; t++) cpa16(dA[t], gA[t]);
    #pragma unroll
    for (int t = 0; t < 2; t++) cpa16(dB[t], gB[t]);
    CP_COMMIT();

    for (int it = 0; it < niter; ++it) {
        if (it + 1 < niter) {
            const int st = (it + 1) & 1;
            const int k0 = (it + 1) << 5;
            #pragma unroll
            for (int t = 0; t < NA; t++) cpa16(dA[t] + st * stgA, gA[t] + k0);
            #pragma unroll
            for (int t = 0; t < 2; t++) cpa16(dB[t] + st * stgB, gB[t] + k0);
            CP_COMMIT();
            CP_WAIT(1);
        } else {
            CP_WAIT(0);
        }
        __syncthreads();

        const uint32_t* as = As[it & 1];
        const uint32_t* bs = Bs[it & 1];
        #pragma unroll
        for (int ks = 0; ks < 2; ks++) {
            const int kb = ks * 8;
            uint32_t af[2][4];
            #pragma unroll
            for (int mi = 0; mi < 2; mi++) {
                int rb = wm * 32 + mi * 16;
                af[mi][0] = as[(rb + g    ) * HSTR + kb + tig    ];
                af[mi][1] = as[(rb + g + 8) * HSTR + kb + tig    ];
                af[mi][2] = as[(rb + g    ) * HSTR + kb + 4 + tig];
                af[mi][3] = as[(rb + g + 8) * HSTR + kb + 4 + tig];
            }
            #pragma unroll
            for (int ni = 0; ni < NI; ni++) {
                int cb = wn * (NI * 8) + ni * 8;
                uint32_t bf[2];
                bf[0] = bs[(cb + g) * HSTR + kb + tig    ];
                bf[1] = bs[(cb + g) * HSTR + kb + 4 + tig];
                #pragma unroll
                for (int mi = 0; mi < 2; mi++) mma_bf16(acc[mi][ni], af[mi], bf);
            }
        }
        __syncthreads();
    }

    #pragma unroll
    for (int mi = 0; mi < 2; mi++) {
        #pragma unroll
        for (int gg = 0; gg < 2; gg++) {
            int r = row0 + wm * 32 + mi * 16 + g + gg * 8;
            #pragma unroll
            for (int ni = 0; ni < NI; ni++) {
                int c = col0 + wn * (NI * 8) + ni * 8 + tig * 2;
                float2 v;
                v.x = acc[mi][ni][gg * 2 + 0] * scale;
                v.y = acc[mi][ni][gg * 2 + 1] * scale;
                *(float2*)(C + (size_t)r * ldc + c) = v;
            }
        }
    }
}

// ================= V transpose + bf16 convert =================
__global__ void transpose_v(const float* __restrict__ V, unsigned short* __restrict__ Vt)
{
    __shared__ float t[32][33];
    int x = blockIdx.x * 32 + threadIdx.x;   // col in V
    int y0 = blockIdx.y * 32;                // row block in V
    for (int dy = threadIdx.y; dy < 32; dy += 8)
        t[dy][threadIdx.x] = V[(size_t)(y0 + dy) * DIM + x];
    __syncthreads();
    int xo = blockIdx.y * 32 + threadIdx.x;  // col in Vt
    int yo0 = blockIdx.x * 32;               // row block in Vt
    __nv_bfloat16* out = (__nv_bfloat16*)Vt;
    for (int dy = threadIdx.y; dy < 32; dy += 8)
        out[(size_t)(yo0 + dy) * NTOK + xo] = __float2bfloat16(t[threadIdx.x][dy]);
}

// ================= combine: sums + Wa avg + Gaussian + stats =================
__global__ void zero_stats_kernel() { g_stats[0] = 0.0; g_stats[1] = 0.0; }

__global__ __launch_bounds__(256) void wf_combine_kernel(const float* __restrict__ dd)
{
    __shared__ float red[NHEAD * 8];
    __shared__ float invZ[NHEAD];
    __shared__ float redA[8], redB[8];
    const int i = blockIdx.x, tid = threadIdx.x;
    const int lane = tid & 31, wid = tid >> 5;
    const int NP2 = NTOK / 2;                       // half2 per row
    const size_t PL2 = (size_t)NTOK * NTOK / 2;     // half2 per plane
    const __half2* planes = (const __half2*)g_Shx;
    const size_t rowoff = (size_t)i * NP2;

    // pass 1: per-head row sums
    float sm[NHEAD];
    #pragma unroll
    for (int h = 0; h < NHEAD; h++) sm[h] = 0.f;
    for (int j = tid; j < NP2; j += 256) {
        #pragma unroll
        for (int h = 0; h < NHEAD; h++) {
            float2 e = __half22float2(planes[h * PL2 + rowoff + j]);
            sm[h] += e.x + e.y;
        }
    }
    #pragma unroll
    for (int h = 0; h < NHEAD; h++) {
        float v = warp_sum(sm[h]);
        if (lane == 0) red[h * 8 + wid] = v;
    }
    __syncthreads();
    if (tid < 96) {
        float v = red[tid];
        v += __shfl_xor_sync(0xffffffffu, v, 1);
        v += __shfl_xor_sync(0xffffffffu, v, 2);
        v += __shfl_xor_sync(0xffffffffu, v, 4);
        if ((tid & 7) == 0) invZ[tid >> 3] = 1.f / (v * (float)NHEAD);
    }
    __syncthreads();

    float iz[NHEAD];
    #pragma unroll
    for (int h = 0; h < NHEAD; h++) iz[h] = invZ[h];

    // pass 2: Wa avg, Gaussian, Wf, stats (re-reads hit L2)
    const float2* drow = (const float2*)(dd + (size_t)i * NTOK);
    float2* frow = (float2*)(g_Wf + (size_t)i * NTOK);
    float s1 = 0.f, s2 = 0.f;
    for (int j = tid; j < NP2; j += 256) {
        float wa0 = 0.f, wa1 = 0.f;
        #pragma unroll
        for (int h = 0; h < NHEAD; h++) {
            float2 e = __half22float2(planes[h * PL2 + rowoff + j]);
            wa0 += e.x * iz[h];
            wa1 += e.y * iz[h];
        }
        float2 d = drow[j];
        float wf0 = __expf(-0.5f * d.x * d.x) * wa0;
        float wf1 = __expf(-0.5f * d.y * d.y) * wa1;
        float2 w; w.x = wf0; w.y = wf1;
        frow[j] = w;
        s1 += wf0 + wf1;
        s2 += wf0 * wf0 + wf1 * wf1;
    }
    s1 = warp_sum(s1);
    s2 = warp_sum(s2);
    if (lane == 0) { redA[wid] = s1; redB[wid] = s2; }
    __syncthreads();
    if (wid == 0) {
        float a = (lane < 8) ? redA[lane] : 0.f;
        float b = (lane < 8) ? redB[lane] : 0.f;
        a = warp_sum(a);
        b = warp_sum(b);
        if (lane == 0) {
            atomicAdd(&g_stats[0], (double)a);
            atomicAdd(&g_stats[1], (double)b);
        }
    }
}

// ================= masked softmax (no shift) -> bf16 attn =================
__global__ __launch_bounds__(256) void masked_softmax_kernel()
{
    __shared__ float2 z[NTOK / 2];
    __shared__ float redB[8];
    __shared__ float sh_thr;
    const int i = blockIdx.x, tid = threadIdx.x;
    const int lane = tid & 31, wid = tid >> 5;
    const int NP2 = NTOK / 2;

    if (tid == 0) {
        double cnt = (double)NTOK * (double)NTOK;
        double mean = g_stats[0] / cnt;
        double var = (g_stats[1] - g_stats[0] * g_stats[0] / cnt) / (cnt - 1.0);
        if (var < 0.0) var = 0.0;
        sh_thr = (float)(mean + 0.5 * sqrt(var));
    }
    __syncthreads();
    const float thr = sh_thr;
    const float invthr = 1.f / thr;

    const float2* srow = (const float2*)(g_S + (size_t)i * NTOK);
    const float2* frow = (const float2*)(g_Wf + (size_t)i * NTOK);

    float lsum = 0.f;
    for (int j = tid; j < NP2; j += 256) {
        float2 wf = frow[j];
        float2 s = srow[j];
        float w0 = (wf.x < thr) ? wf.x * invthr : 1.f;
        float w1 = (wf.y < thr) ? wf.y * invthr : 1.f;
        float e0 = __expf(s.x * w0);
        float e1 = __expf(s.y * w1);
        float2 e; e.x = e0; e.y = e1;
        z[j] = e;
        lsum += e0 + e1;
    }
    lsum = warp_sum(lsum);
    if (lane == 0) redB[wid] = lsum;
    __syncthreads();
    if (wid == 0) {
        float t = (lane < 8) ? redB[lane] : 0.f;
        t = warp_sum(t);
        if (lane == 0) redB[0] = t;
    }
    __syncthreads();
    const float invs = 1.f / redB[0];

    __nv_bfloat162* arow = (__nv_bfloat162*)((__nv_bfloat16*)g_Att + (size_t)i * NTOK);
    for (int j = tid; j < NP2; j += 256) {
        float2 e = z[j];
        arow[j] = __float22bfloat162_rn(make_float2(e.x * invs, e.y * invs));
    }
}

// ================= residual + LayerNorm =================
__global__ __launch_bounds__(256) void ln_kernel(
    const float* __restrict__ hs,
    const float* __restrict__ gamma,
    const float* __restrict__ beta,
    float* __restrict__ out)
{
    const int i = blockIdx.x, tid = threadIdx.x;
    const int lane = tid & 31, wid = tid >> 5;
    __shared__ float r1[8], r2[8];

    const float* orow = g_O + (size_t)i * DIM;
    const float* srow = hs + (size_t)i * DIM;

    float x[3];
    float s = 0.f, ss = 0.f;
    #pragma unroll
    for (int t = 0; t < 3; t++) {
        int c = tid + t * 256;
        x[t] = srow[c] + orow[c];
        s += x[t];
        ss += x[t] * x[t];
    }
    s = warp_sum(s);
    ss = warp_sum(ss);
    if (lane == 0) { r1[wid] = s; r2[wid] = ss; }
    __syncthreads();
    if (wid == 0) {
        float a = (lane < 8) ? r1[lane] : 0.f;
        float b = (lane < 8) ? r2[lane] : 0.f;
        a = warp_sum(a);
        b = warp_sum(b);
        if (lane == 0) { r1[0] = a; r2[0] = b; }
    }
    __syncthreads();
    const float mu = r1[0] * (1.f / DIM);
    const float var = r2[0] * (1.f / DIM) - mu * mu;
    const float inv = rsqrtf(var + 1e-5f);

    #pragma unroll
    for (int t = 0; t < 3; t++) {
        int c = tid + t * 256;
        out[(size_t)i * DIM + c] = (x[t] - mu) * inv * gamma[c] + beta[c];
    }
}

// ================= host =================
extern "C" void kernel_launch(void* const* d_in, const int* in_sizes, int n_in,
                              void* d_out, int out_size)
{
    const float* h_a  = (const float*)d_in[0];
    const float* h_s  = (const float*)d_in[1];
    const float* dep  = (const float*)d_in[2];
    const float* Wq_a = (const float*)d_in[3];
    const float* bq_a = (const float*)d_in[4];
    const float* Wk_a = (const float*)d_in[5];
    const float* bk_a = (const float*)d_in[6];
    const float* Wq   = (const float*)d_in[7];
    const float* bq   = (const float*)d_in[8];
    const float* Wk   = (const float*)d_in[9];
    const float* bk   = (const float*)d_in[10];
    const float* Wv   = (const float*)d_in[11];
    const float* bv   = (const float*)d_in[12];
    const float* lng  = (const float*)d_in[13];
    const float* lnb  = (const float*)d_in[14];
    float* out = (float*)d_out;

    float *qa, *ka, *V, *O, *S;
    unsigned short *Qb, *Kb, *Vt, *Att, *Shx;
    cudaGetSymbolAddress((void**)&qa,  g_qa);
    cudaGetSymbolAddress((void**)&ka,  g_ka);
    cudaGetSymbolAddress((void**)&Qb,  g_Qb);
    cudaGetSymbolAddress((void**)&Kb,  g_Kb);
    cudaGetSymbolAddress((void**)&V,   g_V);
    cudaGetSymbolAddress((void**)&Vt,  g_Vt);
    cudaGetSymbolAddress((void**)&O,   g_O);
    cudaGetSymbolAddress((void**)&S,   g_S);
    cudaGetSymbolAddress((void**)&Att, g_Att);
    cudaGetSymbolAddress((void**)&Shx, g_Shx);

    static cudaStream_t s1;
    static cudaEvent_t e0, e1;
    static int inited = 0;
    if (!inited) {
        cudaStreamCreateWithFlags(&s1, cudaStreamNonBlocking);
        cudaEventCreateWithFlags(&e0, cudaEventDisableTiming);
        cudaEventCreateWithFlags(&e1, cudaEventDisableTiming);
        inited = 1;
    }

    const dim3 blk(256);
    const dim3 gProj(DIM / 128, NTOK / 128);    // 6 x 24
    const dim3 gNN(NTOK / 128, NTOK / 128);     // 24 x 24
    const dim3 gAV(DIM / 128, NTOK / 64);       // 6 x 48

    cudaEventRecord(e0, 0);
    cudaStreamWaitEvent(s1, e0, 0);

    // ---- chain A (s1): structural attention weights ----
    zero_stats_kernel<<<1, 1, 0, s1>>>();
    gemm_nt_tc<float><<<gProj, blk, 0, s1>>>(h_a, DIM, Wq_a, DIM, qa, DIM, DIM, bq_a, 1.f);
    gemm_nt_tc<float><<<gProj, blk, 0, s1>>>(h_a, DIM, Wk_a, DIM, ka, DIM, DIM, bk_a, 1.f);
    heads_gemm<<<gNN, blk, 0, s1>>>(qa, ka, Shx);
    wf_combine_kernel<<<NTOK, 256, 0, s1>>>(dep);
    cudaEventRecord(e1, s1);

    // ---- chain B (default): guided attention ----
    gemm_nt_tc<__nv_bfloat16><<<gProj, blk>>>(h_s, DIM, Wq, DIM, (__nv_bfloat16*)Qb, DIM, DIM, bq, 1.f);
    gemm_nt_tc<__nv_bfloat16><<<gProj, blk>>>(h_s, DIM, Wk, DIM, (__nv_bfloat16*)Kb, DIM, DIM, bk, 1.f);
    gemm_nt_tc<float><<<gProj, blk>>>(h_s, DIM, Wv, DIM, V, DIM, DIM, bv, 1.f);
    transpose_v<<<dim3(DIM / 32, NTOK / 32), dim3(32, 8)>>>(V, Vt);
    const float score_scale = 1.f / sqrtf((float)DIM);
    gemm_nt_bf<128><<<gNN, blk>>>(Qb, DIM, Kb, DIM, S, NTOK, DIM, score_scale);

    // join, then tail
    cudaStreamWaitEvent(0, e1, 0);
    masked_softmax_kernel<<<NTOK, 256>>>();
    gemm_nt_bf<64><<<gAV, blk>>>(Att, NTOK, Vt, NTOK, O, DIM, NTOK, 1.f);
    ln_kernel<<<NTOK, 256>>>(h_s, lng, lnb, out);
}

// round 6
// speedup vs baseline: 3.5016x; 1.2484x over previous
#include <cuda_runtime.h>
#include <cuda_fp16.h>
#include <cuda_bf16.h>
#include <math.h>
#include <stdint.h>

#define NTOK 3072
#define DIM  768
#define NHEAD 12
#define HDIM 64

// ---------------- static device scratch ----------------
__device__ unsigned short g_hab[NTOK * DIM];   // h_a bf16
__device__ unsigned short g_hsb[NTOK * DIM];   // h_s bf16
__device__ unsigned short g_Wqab[DIM * DIM];
__device__ unsigned short g_Wkab[DIM * DIM];
__device__ unsigned short g_Wqb [DIM * DIM];
__device__ unsigned short g_Wkb [DIM * DIM];
__device__ unsigned short g_Wvb [DIM * DIM];
__device__ unsigned short g_qab[NTOK * DIM];   // qa bf16
__device__ unsigned short g_kab[NTOK * DIM];   // ka bf16
__device__ unsigned short g_Qb [NTOK * DIM];   // Q bf16
__device__ unsigned short g_Kb [NTOK * DIM];   // K bf16
__device__ unsigned short g_Vb [NTOK * DIM];   // V bf16
__device__ unsigned short g_Vt [DIM * NTOK];   // V^T bf16
__device__ float g_O [NTOK * DIM];
__device__ float g_S [(size_t)NTOK * NTOK];               // fp32 scores
__device__ unsigned short g_Att[(size_t)NTOK * NTOK];     // bf16 attn
__device__ unsigned short g_Shx[(size_t)NHEAD * NTOK * NTOK]; // fp16 exp planes
__device__ float g_Wf[(size_t)NTOK * NTOK];
__device__ float g_rsum[NHEAD * NTOK];                    // per-head exp row sums
__device__ double g_stats[2];

// ---------------- helpers ----------------
__device__ __forceinline__ float warp_sum(float v) {
    #pragma unroll
    for (int o = 16; o; o >>= 1) v += __shfl_xor_sync(0xffffffffu, v, o);
    return v;
}
__device__ __forceinline__ void mma_bf16(float* d, const uint32_t* a, const uint32_t* b) {
    asm volatile(
        "mma.sync.aligned.m16n8k16.row.col.f32.bf16.bf16.f32 "
        "{%0,%1,%2,%3}, {%4,%5,%6,%7}, {%8,%9}, {%0,%1,%2,%3};\n"
        : "+f"(d[0]), "+f"(d[1]), "+f"(d[2]), "+f"(d[3])
        : "r"(a[0]), "r"(a[1]), "r"(a[2]), "r"(a[3]), "r"(b[0]), "r"(b[1]));
}
__device__ __forceinline__ void cpa16(uint32_t smem, const void* gptr) {
    asm volatile("cp.async.ca.shared.global [%0], [%1], 16;\n" :: "r"(smem), "l"(gptr));
}
#define CP_COMMIT()  asm volatile("cp.async.commit_group;\n")
#define CP_WAIT(N)   asm volatile("cp.async.wait_group %0;\n" :: "n"(N))

#define HSTR 20   // bf16 tile row stride in b32 units (16 data + 4 pad): conflict-free

// ---------------- fp32 -> bf16 conversion (vectorized) ----------------
__global__ void f2b_kernel(const float4* __restrict__ in, uint2* __restrict__ outp, int n4)
{
    int i = blockIdx.x * blockDim.x + threadIdx.x;
    if (i < n4) {
        float4 v = in[i];
        __nv_bfloat162 a = __float22bfloat162_rn(make_float2(v.x, v.y));
        __nv_bfloat162 b = __float22bfloat162_rn(make_float2(v.z, v.w));
        uint2 u;
        u.x = *(uint32_t*)&a;
        u.y = *(uint32_t*)&b;
        outp[i] = u;
    }
}

// ================= bf16 TC NT GEMM: C = scale*A.B^T (+bias) =================
// A [M x K] row-major bf16, B [N x K] row-major bf16. BK=32 halves, double-buffered.
template <int BM, typename OutT>
__global__ __launch_bounds__(256, 2) void gemm_nt_bf(
    const unsigned short* __restrict__ A, int lda,
    const unsigned short* __restrict__ B, int ldb,
    OutT* __restrict__ C, int ldc, int K,
    const float* __restrict__ bias, float scale)
{
    constexpr int WMN = BM / 32;
    constexpr int WNN = 8 / WMN;
    constexpr int NI  = 128 / (WNN * 8);
    constexpr int NA  = BM * 4 / 256;

    __shared__ uint32_t As[2][BM * HSTR];
    __shared__ uint32_t Bs[2][128 * HSTR];

    const int tid = threadIdx.x;
    const int row0 = blockIdx.y * BM, col0 = blockIdx.x * 128;
    const int wid = tid >> 5, lane = tid & 31;
    const int wm = wid % WMN, wn = wid / WMN;
    const int g = lane >> 2, tig = lane & 3;

    float acc[2][NI][4];
    #pragma unroll
    for (int i = 0; i < 2; i++)
        #pragma unroll
        for (int j = 0; j < NI; j++)
            #pragma unroll
            for (int q = 0; q < 4; q++) acc[i][j][q] = 0.f;

    const uint32_t sA = (uint32_t)__cvta_generic_to_shared(&As[0][0]);
    const uint32_t sB = (uint32_t)__cvta_generic_to_shared(&Bs[0][0]);
    const uint32_t stgA = BM * HSTR * 4;
    const uint32_t stgB = 128 * HSTR * 4;

    const unsigned short* gA[NA];
    uint32_t dA[NA];
    #pragma unroll
    for (int t = 0; t < NA; t++) {
        int ch = tid + t * 256;
        int cr = ch >> 2, cc = ch & 3;
        gA[t] = A + (size_t)(row0 + cr) * lda + cc * 8;
        dA[t] = sA + (cr * HSTR + cc * 4) * 4;
    }
    const unsigned short* gB[2];
    uint32_t dB[2];
    #pragma unroll
    for (int t = 0; t < 2; t++) {
        int ch = tid + t * 256;
        int cr = ch >> 2, cc = ch & 3;
        gB[t] = B + (size_t)(col0 + cr) * ldb + cc * 8;
        dB[t] = sB + (cr * HSTR + cc * 4) * 4;
    }

    const int niter = K >> 5;

    #pragma unroll
    for (int t = 0; t < NA; t++) cpa16(dA[t], gA[t]);
    #pragma unroll
    for (int t = 0; t < 2; t++) cpa16(dB[t], gB[t]);
    CP_COMMIT();

    for (int it = 0; it < niter; ++it) {
        if (it + 1 < niter) {
            const int st = (it + 1) & 1;
            const int k0 = (it + 1) << 5;
            #pragma unroll
            for (int t = 0; t < NA; t++) cpa16(dA[t] + st * stgA, gA[t] + k0);
            #pragma unroll
            for (int t = 0; t < 2; t++) cpa16(dB[t] + st * stgB, gB[t] + k0);
            CP_COMMIT();
            CP_WAIT(1);
        } else {
            CP_WAIT(0);
        }
        __syncthreads();

        const uint32_t* as = As[it & 1];
        const uint32_t* bs = Bs[it & 1];
        #pragma unroll
        for (int ks = 0; ks < 2; ks++) {
            const int kb = ks * 8;
            uint32_t af[2][4];
            #pragma unroll
            for (int mi = 0; mi < 2; mi++) {
                int rb = wm * 32 + mi * 16;
                af[mi][0] = as[(rb + g    ) * HSTR + kb + tig    ];
                af[mi][1] = as[(rb + g + 8) * HSTR + kb + tig    ];
                af[mi][2] = as[(rb + g    ) * HSTR + kb + 4 + tig];
                af[mi][3] = as[(rb + g + 8) * HSTR + kb + 4 + tig];
            }
            #pragma unroll
            for (int ni = 0; ni < NI; ni++) {
                int cb = wn * (NI * 8) + ni * 8;
                uint32_t bf[2];
                bf[0] = bs[(cb + g) * HSTR + kb + tig    ];
                bf[1] = bs[(cb + g) * HSTR + kb + 4 + tig];
                #pragma unroll
                for (int mi = 0; mi < 2; mi++) mma_bf16(acc[mi][ni], af[mi], bf);
            }
        }
        __syncthreads();
    }

    #pragma unroll
    for (int mi = 0; mi < 2; mi++) {
        #pragma unroll
        for (int gg = 0; gg < 2; gg++) {
            int r = row0 + wm * 32 + mi * 16 + g + gg * 8;
            #pragma unroll
            for (int ni = 0; ni < NI; ni++) {
                int c = col0 + wn * (NI * 8) + ni * 8 + tig * 2;
                float vx = acc[mi][ni][gg * 2 + 0] * scale;
                float vy = acc[mi][ni][gg * 2 + 1] * scale;
                if (bias) { vx += bias[c]; vy += bias[c + 1]; }
                if constexpr (sizeof(OutT) == 2) {
                    __nv_bfloat162 bv = __float22bfloat162_rn(make_float2(vx, vy));
                    *(uint32_t*)((unsigned short*)C + (size_t)r * ldc + c) = *(uint32_t*)&bv;
                } else {
                    float2 v; v.x = vx; v.y = vy;
                    *(float2*)((float*)C + (size_t)r * ldc + c) = v;
                }
            }
        }
    }
}

// ================= fused 12-head logits GEMM (bf16) + exp epilogue + row sums =================
__global__ __launch_bounds__(256, 2) void heads_gemm_bf(
    const unsigned short* __restrict__ A,   // qa bf16 [3072 x 768]
    const unsigned short* __restrict__ B,   // ka bf16 [3072 x 768]
    unsigned short* __restrict__ P,         // 12 fp16 exp planes
    float* __restrict__ rsum)               // [NHEAD][NTOK]
{
    __shared__ uint32_t As[2][128 * HSTR];
    __shared__ uint32_t Bs[2][128 * HSTR];

    const int tid = threadIdx.x;
    const int row0 = blockIdx.y * 128, col0 = blockIdx.x * 128;
    const int wid = tid >> 5, lane = tid & 31;
    const int wm = wid & 3, wn = wid >> 2;
    const int g = lane >> 2, tig = lane & 3;

    const uint32_t sA = (uint32_t)__cvta_generic_to_shared(&As[0][0]);
    const uint32_t sB = (uint32_t)__cvta_generic_to_shared(&Bs[0][0]);
    const uint32_t stg = 128 * HSTR * 4;

    const unsigned short* gA[2];
    uint32_t dA[2];
    const unsigned short* gB[2];
    uint32_t dB[2];
    #pragma unroll
    for (int t = 0; t < 2; t++) {
        int ch = tid + t * 256;
        int cr = ch >> 2, cc = ch & 3;
        gA[t] = A + (size_t)(row0 + cr) * DIM + cc * 8;
        dA[t] = sA + (cr * HSTR + cc * 4) * 4;
        gB[t] = B + (size_t)(col0 + cr) * DIM + cc * 8;
        dB[t] = sB + (cr * HSTR + cc * 4) * 4;
    }

    const int niter = DIM >> 5;  // 24 = 12 heads x 2

    #pragma unroll
    for (int t = 0; t < 2; t++) { cpa16(dA[t], gA[t]); cpa16(dB[t], gB[t]); }
    CP_COMMIT();

    for (int h = 0; h < NHEAD; h++) {
        float acc[2][8][4];
        #pragma unroll
        for (int i = 0; i < 2; i++)
            #pragma unroll
            for (int j = 0; j < 8; j++)
                #pragma unroll
                for (int q = 0; q < 4; q++) acc[i][j][q] = 0.f;

        #pragma unroll
        for (int ki = 0; ki < 2; ki++) {
            const int it = h * 2 + ki;
            if (it + 1 < niter) {
                const int st = (it + 1) & 1;
                const int k0 = (it + 1) << 5;
                #pragma unroll
                for (int t = 0; t < 2; t++) {
                    cpa16(dA[t] + st * stg, gA[t] + k0);
                    cpa16(dB[t] + st * stg, gB[t] + k0);
                }
                CP_COMMIT();
                CP_WAIT(1);
            } else {
                CP_WAIT(0);
            }
            __syncthreads();

            const uint32_t* as = As[it & 1];
            const uint32_t* bs = Bs[it & 1];
            #pragma unroll
            for (int ks = 0; ks < 2; ks++) {
                const int kb = ks * 8;
                uint32_t af[2][4];
                #pragma unroll
                for (int mi = 0; mi < 2; mi++) {
                    int rb = wm * 32 + mi * 16;
                    af[mi][0] = as[(rb + g    ) * HSTR + kb + tig    ];
                    af[mi][1] = as[(rb + g + 8) * HSTR + kb + tig    ];
                    af[mi][2] = as[(rb + g    ) * HSTR + kb + 4 + tig];
                    af[mi][3] = as[(rb + g + 8) * HSTR + kb + 4 + tig];
                }
                #pragma unroll
                for (int ni = 0; ni < 8; ni++) {
                    int cb = wn * 64 + ni * 8;
                    uint32_t bf[2];
                    bf[0] = bs[(cb + g) * HSTR + kb + tig    ];
                    bf[1] = bs[(cb + g) * HSTR + kb + 4 + tig];
                    #pragma unroll
                    for (int mi = 0; mi < 2; mi++) mma_bf16(acc[mi][ni], af[mi], bf);
                }
            }
            __syncthreads();
        }

        // epilogue: exp(logit/8) -> fp16 plane, plus per-row sum accumulation
        __half* plane = (__half*)P + (size_t)h * NTOK * NTOK;
        float* rs_h = rsum + h * NTOK;
        #pragma unroll
        for (int mi = 0; mi < 2; mi++) {
            #pragma unroll
            for (int gg = 0; gg < 2; gg++) {
                int r = row0 + wm * 32 + mi * 16 + g + gg * 8;
                float rowacc = 0.f;
                #pragma unroll
                for (int ni = 0; ni < 8; ni++) {
                    int c = col0 + wn * 64 + ni * 8 + tig * 2;
                    float e0 = __expf(0.125f * acc[mi][ni][gg * 2 + 0]);
                    float e1 = __expf(0.125f * acc[mi][ni][gg * 2 + 1]);
                    *(__half2*)(plane + (size_t)r * NTOK + c) = __floats2half2_rn(e0, e1);
                    rowacc += e0 + e1;
                }
                // quad reduce over tig (lanes g*4 + tig)
                rowacc += __shfl_xor_sync(0xffffffffu, rowacc, 1);
                rowacc += __shfl_xor_sync(0xffffffffu, rowacc, 2);
                if (tig == 0) atomicAdd(&rs_h[r], rowacc);
            }
        }
    }
}

// ================= V transpose (bf16 -> bf16) =================
__global__ void transpose_v(const unsigned short* __restrict__ V, unsigned short* __restrict__ Vt)
{
    __shared__ unsigned short t[32][34];
    int x = blockIdx.x * 32 + threadIdx.x;
    int y0 = blockIdx.y * 32;
    for (int dy = threadIdx.y; dy < 32; dy += 8)
        t[dy][threadIdx.x] = V[(size_t)(y0 + dy) * DIM + x];
    __syncthreads();
    int xo = blockIdx.y * 32 + threadIdx.x;
    int yo0 = blockIdx.x * 32;
    for (int dy = threadIdx.y; dy < 32; dy += 8)
        Vt[(size_t)(yo0 + dy) * NTOK + xo] = t[threadIdx.x][dy];
}

// ================= zero rsum + stats =================
__global__ void zero_kernel(float* __restrict__ rsum)
{
    int i = blockIdx.x * blockDim.x + threadIdx.x;
    if (i < NHEAD * NTOK) rsum[i] = 0.f;
    if (i == 0) { g_stats[0] = 0.0; g_stats[1] = 0.0; }
}

// ================= combine: Wa avg + Gaussian + stats (single pass) =================
__global__ __launch_bounds__(256) void wf_combine_kernel(
    const float* __restrict__ dd, const float* __restrict__ rsum)
{
    __shared__ float shInv[NHEAD];
    __shared__ float redA[8], redB[8];
    const int i = blockIdx.x, tid = threadIdx.x;
    const int lane = tid & 31, wid = tid >> 5;
    const int NP2 = NTOK / 2;
    const size_t PL2 = (size_t)NTOK * NTOK / 2;
    const __half2* planes = (const __half2*)g_Shx;
    const size_t rowoff = (size_t)i * NP2;

    if (tid < NHEAD) shInv[tid] = 1.f / (rsum[tid * NTOK + i] * (float)NHEAD);
    __syncthreads();

    float iz[NHEAD];
    #pragma unroll
    for (int h = 0; h < NHEAD; h++) iz[h] = shInv[h];

    const float2* drow = (const float2*)(dd + (size_t)i * NTOK);
    float2* frow = (float2*)(g_Wf + (size_t)i * NTOK);
    float s1 = 0.f, s2 = 0.f;
    for (int j = tid; j < NP2; j += 256) {
        float wa0 = 0.f, wa1 = 0.f;
        #pragma unroll
        for (int h = 0; h < NHEAD; h++) {
            float2 e = __half22float2(planes[h * PL2 + rowoff + j]);
            wa0 += e.x * iz[h];
            wa1 += e.y * iz[h];
        }
        float2 d = drow[j];
        float wf0 = __expf(-0.5f * d.x * d.x) * wa0;
        float wf1 = __expf(-0.5f * d.y * d.y) * wa1;
        float2 w; w.x = wf0; w.y = wf1;
        frow[j] = w;
        s1 += wf0 + wf1;
        s2 += wf0 * wf0 + wf1 * wf1;
    }
    s1 = warp_sum(s1);
    s2 = warp_sum(s2);
    if (lane == 0) { redA[wid] = s1; redB[wid] = s2; }
    __syncthreads();
    if (wid == 0) {
        float a = (lane < 8) ? redA[lane] : 0.f;
        float b = (lane < 8) ? redB[lane] : 0.f;
        a = warp_sum(a);
        b = warp_sum(b);
        if (lane == 0) {
            atomicAdd(&g_stats[0], (double)a);
            atomicAdd(&g_stats[1], (double)b);
        }
    }
}

// ================= masked softmax (no shift) -> bf16 attn =================
__global__ __launch_bounds__(256) void masked_softmax_kernel()
{
    __shared__ float2 z[NTOK / 2];
    __shared__ float redB[8];
    __shared__ float sh_thr;
    const int i = blockIdx.x, tid = threadIdx.x;
    const int lane = tid & 31, wid = tid >> 5;
    const int NP2 = NTOK / 2;

    if (tid == 0) {
        double cnt = (double)NTOK * (double)NTOK;
        double mean = g_stats[0] / cnt;
        double var = (g_stats[1] - g_stats[0] * g_stats[0] / cnt) / (cnt - 1.0);
        if (var < 0.0) var = 0.0;
        sh_thr = (float)(mean + 0.5 * sqrt(var));
    }
    __syncthreads();
    const float thr = sh_thr;
    const float invthr = 1.f / thr;

    const float2* srow = (const float2*)(g_S + (size_t)i * NTOK);
    const float2* frow = (const float2*)(g_Wf + (size_t)i * NTOK);

    float lsum = 0.f;
    for (int j = tid; j < NP2; j += 256) {
        float2 wf = frow[j];
        float2 s = srow[j];
        float w0 = (wf.x < thr) ? wf.x * invthr : 1.f;
        float w1 = (wf.y < thr) ? wf.y * invthr : 1.f;
        float e0 = __expf(s.x * w0);
        float e1 = __expf(s.y * w1);
        float2 e; e.x = e0; e.y = e1;
        z[j] = e;
        lsum += e0 + e1;
    }
    lsum = warp_sum(lsum);
    if (lane == 0) redB[wid] = lsum;
    __syncthreads();
    if (wid == 0) {
        float t = (lane < 8) ? redB[lane] : 0.f;
        t = warp_sum(t);
        if (lane == 0) redB[0] = t;
    }
    __syncthreads();
    const float invs = 1.f / redB[0];

    uint32_t* arow = (uint32_t*)((unsigned short*)g_Att + (size_t)i * NTOK);
    for (int j = tid; j < NP2; j += 256) {
        float2 e = z[j];
        __nv_bfloat162 bv = __float22bfloat162_rn(make_float2(e.x * invs, e.y * invs));
        arow[j] = *(uint32_t*)&bv;
    }
}

// ================= residual + LayerNorm =================
__global__ __launch_bounds__(256) void ln_kernel(
    const float* __restrict__ hs,
    const float* __restrict__ gamma,
    const float* __restrict__ beta,
    float* __restrict__ out)
{
    const int i = blockIdx.x, tid = threadIdx.x;
    const int lane = tid & 31, wid = tid >> 5;
    __shared__ float r1[8], r2[8];

    const float* orow = g_O + (size_t)i * DIM;
    const float* srow = hs + (size_t)i * DIM;

    float x[3];
    float s = 0.f, ss = 0.f;
    #pragma unroll
    for (int t = 0; t < 3; t++) {
        int c = tid + t * 256;
        x[t] = srow[c] + orow[c];
        s += x[t];
        ss += x[t] * x[t];
    }
    s = warp_sum(s);
    ss = warp_sum(ss);
    if (lane == 0) { r1[wid] = s; r2[wid] = ss; }
    __syncthreads();
    if (wid == 0) {
        float a = (lane < 8) ? r1[lane] : 0.f;
        float b = (lane < 8) ? r2[lane] : 0.f;
        a = warp_sum(a);
        b = warp_sum(b);
        if (lane == 0) { r1[0] = a; r2[0] = b; }
    }
    __syncthreads();
    const float mu = r1[0] * (1.f / DIM);
    const float var = r2[0] * (1.f / DIM) - mu * mu;
    const float inv = rsqrtf(var + 1e-5f);

    #pragma unroll
    for (int t = 0; t < 3; t++) {
        int c = tid + t * 256;
        out[(size_t)i * DIM + c] = (x[t] - mu) * inv * gamma[c] + beta[c];
    }
}

// ================= host =================
extern "C" void kernel_launch(void* const* d_in, const int* in_sizes, int n_in,
                              void* d_out, int out_size)
{
    const float* h_a  = (const float*)d_in[0];
    const float* h_s  = (const float*)d_in[1];
    const float* dep  = (const float*)d_in[2];
    const float* Wq_a = (const float*)d_in[3];
    const float* bq_a = (const float*)d_in[4];
    const float* Wk_a = (const float*)d_in[5];
    const float* bk_a = (const float*)d_in[6];
    const float* Wq   = (const float*)d_in[7];
    const float* bq   = (const float*)d_in[8];
    const float* Wk   = (const float*)d_in[9];
    const float* bk   = (const float*)d_in[10];
    const float* Wv   = (const float*)d_in[11];
    const float* bv   = (const float*)d_in[12];
    const float* lng  = (const float*)d_in[13];
    const float* lnb  = (const float*)d_in[14];
    float* out = (float*)d_out;

    unsigned short *hab, *hsb, *Wqab, *Wkab, *Wqb, *Wkb, *Wvb;
    unsigned short *qab, *kab, *Qb, *Kb, *Vb, *Vt, *Att, *Shx;
    float *O, *S, *Wf, *rsum;
    cudaGetSymbolAddress((void**)&hab,  g_hab);
    cudaGetSymbolAddress((void**)&hsb,  g_hsb);
    cudaGetSymbolAddress((void**)&Wqab, g_Wqab);
    cudaGetSymbolAddress((void**)&Wkab, g_Wkab);
    cudaGetSymbolAddress((void**)&Wqb,  g_Wqb);
    cudaGetSymbolAddress((void**)&Wkb,  g_Wkb);
    cudaGetSymbolAddress((void**)&Wvb,  g_Wvb);
    cudaGetSymbolAddress((void**)&qab,  g_qab);
    cudaGetSymbolAddress((void**)&kab,  g_kab);
    cudaGetSymbolAddress((void**)&Qb,   g_Qb);
    cudaGetSymbolAddress((void**)&Kb,   g_Kb);
    cudaGetSymbolAddress((void**)&Vb,   g_Vb);
    cudaGetSymbolAddress((void**)&Vt,   g_Vt);
    cudaGetSymbolAddress((void**)&Att,  g_Att);
    cudaGetSymbolAddress((void**)&Shx,  g_Shx);
    cudaGetSymbolAddress((void**)&O,    g_O);
    cudaGetSymbolAddress((void**)&S,    g_S);
    cudaGetSymbolAddress((void**)&Wf,   g_Wf);
    cudaGetSymbolAddress((void**)&rsum, g_rsum);

    static cudaStream_t s1;
    static cudaEvent_t e0, e1;
    static int inited = 0;
    if (!inited) {
        cudaStreamCreateWithFlags(&s1, cudaStreamNonBlocking);
        cudaEventCreateWithFlags(&e0, cudaEventDisableTiming);
        cudaEventCreateWithFlags(&e1, cudaEventDisableTiming);
        inited = 1;
    }

    const dim3 blk(256);
    const dim3 gProj(DIM / 128, NTOK / 128);    // 6 x 24
    const dim3 gNN(NTOK / 128, NTOK / 128);     // 24 x 24
    const dim3 gAV(DIM / 128, NTOK / 64);       // 6 x 48
    const int NH4 = (NTOK * DIM) / 4;           // 589824
    const int NW4 = (DIM * DIM) / 4;            // 147456

    cudaEventRecord(e0, 0);
    cudaStreamWaitEvent(s1, e0, 0);

    // ---- chain A (s1): structural attention weights ----
    zero_kernel<<<(NHEAD * NTOK + 255) / 256, 256, 0, s1>>>(rsum);
    f2b_kernel<<<(NH4 + 255) / 256, 256, 0, s1>>>((const float4*)h_a, (uint2*)hab, NH4);
    f2b_kernel<<<(NW4 + 255) / 256, 256, 0, s1>>>((const float4*)Wq_a, (uint2*)Wqab, NW4);
    f2b_kernel<<<(NW4 + 255) / 256, 256, 0, s1>>>((const float4*)Wk_a, (uint2*)Wkab, NW4);
    gemm_nt_bf<128, unsigned short><<<gProj, blk, 0, s1>>>(hab, DIM, Wqab, DIM, qab, DIM, DIM, bq_a, 1.f);
    gemm_nt_bf<128, unsigned short><<<gProj, blk, 0, s1>>>(hab, DIM, Wkab, DIM, kab, DIM, DIM, bk_a, 1.f);
    heads_gemm_bf<<<gNN, blk, 0, s1>>>(qab, kab, Shx, rsum);
    wf_combine_kernel<<<NTOK, 256, 0, s1>>>(dep, rsum);
    cudaEventRecord(e1, s1);

    // ---- chain B (default): guided attention ----
    f2b_kernel<<<(NH4 + 255) / 256, 256>>>((const float4*)h_s, (uint2*)hsb, NH4);
    f2b_kernel<<<(NW4 + 255) / 256, 256>>>((const float4*)Wq, (uint2*)Wqb, NW4);
    f2b_kernel<<<(NW4 + 255) / 256, 256>>>((const float4*)Wk, (uint2*)Wkb, NW4);
    f2b_kernel<<<(NW4 + 255) / 256, 256>>>((const float4*)Wv, (uint2*)Wvb, NW4);
    gemm_nt_bf<128, unsigned short><<<gProj, blk>>>(hsb, DIM, Wqb, DIM, Qb, DIM, DIM, bq, 1.f);
    gemm_nt_bf<128, unsigned short><<<gProj, blk>>>(hsb, DIM, Wkb, DIM, Kb, DIM, DIM, bk, 1.f);
    gemm_nt_bf<128, unsigned short><<<gProj, blk>>>(hsb, DIM, Wvb, DIM, Vb, DIM, DIM, bv, 1.f);
    transpose_v<<<dim3(DIM / 32, NTOK / 32), dim3(32, 8)>>>(Vb, Vt);
    const float score_scale = 1.f / sqrtf((float)DIM);
    gemm_nt_bf<128, float><<<gNN, blk>>>(Qb, DIM, Kb, DIM, S, NTOK, DIM, nullptr, score_scale);

    // join, then tail
    cudaStreamWaitEvent(0, e1, 0);
    masked_softmax_kernel<<<NTOK, 256>>>();
    gemm_nt_bf<64, float><<<gAV, blk>>>(Att, NTOK, Vt, NTOK, O, DIM, NTOK, nullptr, 1.f);
    ln_kernel<<<NTOK, 256>>>(h_s, lng, lnb, out);
}

// round 7
// speedup vs baseline: 4.3723x; 1.2487x over previous
#include <cuda_runtime.h>
#include <cuda_fp16.h>
#include <cuda_bf16.h>
#include <math.h>
#include <stdint.h>

#define NTOK 3072
#define DIM  768
#define NHEAD 12
#define HDIM 64

// ---------------- static device scratch ----------------
__device__ unsigned short g_hab[NTOK * DIM];
__device__ unsigned short g_hsb[NTOK * DIM];
__device__ unsigned short g_Wqab[DIM * DIM];
__device__ unsigned short g_Wkab[DIM * DIM];
__device__ unsigned short g_Wqb [DIM * DIM];
__device__ unsigned short g_Wkb [DIM * DIM];
__device__ unsigned short g_Wvb [DIM * DIM];
__device__ unsigned short g_qab[NTOK * DIM];
__device__ unsigned short g_kab[NTOK * DIM];
__device__ unsigned short g_Qb [NTOK * DIM];
__device__ unsigned short g_Kb [NTOK * DIM];
__device__ unsigned short g_Vb [NTOK * DIM];
__device__ unsigned short g_Vt [DIM * NTOK];
__device__ float g_O [NTOK * DIM];
__device__ float g_S [(size_t)NTOK * NTOK];
__device__ unsigned short g_Att[(size_t)NTOK * NTOK];
__device__ unsigned short g_Shx[(size_t)NHEAD * NTOK * NTOK]; // fp16 exp planes
__device__ float g_Wf[(size_t)NTOK * NTOK];
__device__ float g_rsum[NHEAD * NTOK];
__device__ double g_stats[2];

// ---------------- helpers ----------------
__device__ __forceinline__ float warp_sum(float v) {
    #pragma unroll
    for (int o = 16; o; o >>= 1) v += __shfl_xor_sync(0xffffffffu, v, o);
    return v;
}
__device__ __forceinline__ void mma_bf16(float* d, const uint32_t* a, uint32_t b0, uint32_t b1) {
    asm volatile(
        "mma.sync.aligned.m16n8k16.row.col.f32.bf16.bf16.f32 "
        "{%0,%1,%2,%3}, {%4,%5,%6,%7}, {%8,%9}, {%0,%1,%2,%3};\n"
        : "+f"(d[0]), "+f"(d[1]), "+f"(d[2]), "+f"(d[3])
        : "r"(a[0]), "r"(a[1]), "r"(a[2]), "r"(a[3]), "r"(b0), "r"(b1));
}
__device__ __forceinline__ void ldsm_x4(uint32_t* r, uint32_t addr) {
    asm volatile("ldmatrix.sync.aligned.m8n8.x4.shared.b16 {%0,%1,%2,%3}, [%4];"
        : "=r"(r[0]), "=r"(r[1]), "=r"(r[2]), "=r"(r[3]) : "r"(addr));
}
__device__ __forceinline__ void cpa16(uint32_t smem, const void* gptr) {
    asm volatile("cp.async.ca.shared.global [%0], [%1], 16;\n" :: "r"(smem), "l"(gptr));
}
#define CP_COMMIT()  asm volatile("cp.async.commit_group;\n")
#define CP_WAIT(N)   asm volatile("cp.async.wait_group %0;\n" :: "n"(N))

#define HSTR 20         // b32 per smem row (16 data + 4 pad); 80B stride
#define NSTAGE 3

// ---------------- fp32 -> bf16 conversion, multi-array fused ----------------
__global__ void f2b_multi(const float4* a0, uint2* o0, int n0,
                          const float4* a1, uint2* o1, int n1,
                          const float4* a2, uint2* o2, int n2,
                          const float4* a3, uint2* o3, int n3)
{
    int i = blockIdx.x * blockDim.x + threadIdx.x;
    const float4* in; uint2* out; int idx;
    if (i < n0) { in = a0; out = o0; idx = i; }
    else if (i < n0 + n1) { in = a1; out = o1; idx = i - n0; }
    else if (i < n0 + n1 + n2) { in = a2; out = o2; idx = i - n0 - n1; }
    else if (i < n0 + n1 + n2 + n3) { in = a3; out = o3; idx = i - n0 - n1 - n2; }
    else return;
    float4 v = in[idx];
    __nv_bfloat162 a = __float22bfloat162_rn(make_float2(v.x, v.y));
    __nv_bfloat162 b = __float22bfloat162_rn(make_float2(v.z, v.w));
    uint2 u; u.x = *(uint32_t*)&a; u.y = *(uint32_t*)&b;
    out[idx] = u;
}

// ================= bf16 TC NT GEMM (ldmatrix + 3-stage): C = scale*A.B^T (+bias) =================
template <int BM, typename OutT>
__global__ __launch_bounds__(256, 2) void gemm_nt_bf(
    const unsigned short* __restrict__ A, int lda,
    const unsigned short* __restrict__ B, int ldb,
    OutT* __restrict__ C, int ldc, int K,
    const float* __restrict__ bias, float scale)
{
    constexpr int WMN = BM / 32;
    constexpr int WNN = 8 / WMN;
    constexpr int NI  = 128 / (WNN * 8);
    constexpr int NB  = NI / 2;
    constexpr int NA  = BM * 4 / 256;
    constexpr uint32_t stgA = BM * HSTR * 4;
    constexpr uint32_t stgB = 128 * HSTR * 4;

    extern __shared__ uint32_t dynsm[];
    const uint32_t sbase = (uint32_t)__cvta_generic_to_shared(dynsm);
    const uint32_t sA = sbase;
    const uint32_t sB = sbase + NSTAGE * stgA;

    const int tid = threadIdx.x;
    const int row0 = blockIdx.y * BM, col0 = blockIdx.x * 128;
    const int wid = tid >> 5, lane = tid & 31;
    const int wm = wid % WMN, wn = wid / WMN;
    const int g = lane >> 2, tig = lane & 3;
    const int seg = lane >> 3, l7 = lane & 7;

    float acc[2][NI][4];
    #pragma unroll
    for (int i = 0; i < 2; i++)
        #pragma unroll
        for (int j = 0; j < NI; j++)
            #pragma unroll
            for (int q = 0; q < 4; q++) acc[i][j][q] = 0.f;

    // cp.async source/dest
    const unsigned short* gA[NA]; uint32_t dA[NA];
    #pragma unroll
    for (int t = 0; t < NA; t++) {
        int ch = tid + t * 256;
        int cr = ch >> 2, cc = ch & 3;
        gA[t] = A + (size_t)(row0 + cr) * lda + cc * 8;
        dA[t] = sA + cr * 80 + cc * 16;
    }
    const unsigned short* gB[2]; uint32_t dB[2];
    #pragma unroll
    for (int t = 0; t < 2; t++) {
        int ch = tid + t * 256;
        int cr = ch >> 2, cc = ch & 3;
        gB[t] = B + (size_t)(col0 + cr) * ldb + cc * 8;
        dB[t] = sB + cr * 80 + cc * 16;
    }

    // ldmatrix lane addresses (stage-0 relative)
    const int rowA = (seg & 1) * 8 + l7;
    const uint32_t kAb = (seg >> 1) * 16;
    uint32_t aAddr[2];
    #pragma unroll
    for (int mi = 0; mi < 2; mi++)
        aAddr[mi] = sA + (uint32_t)(wm * 32 + mi * 16 + rowA) * 80 + kAb;
    const int rowB = (seg >> 1) * 8 + l7;
    const uint32_t kBb = (seg & 1) * 16;
    uint32_t bAddr[NB];
    #pragma unroll
    for (int nb = 0; nb < NB; nb++)
        bAddr[nb] = sB + (uint32_t)(wn * (NI * 8) + nb * 16 + rowB) * 80 + kBb;

    const int niter = K >> 5;

    // prologue: stages 0,1
    #pragma unroll
    for (int s = 0; s < 2; s++) {
        const int k0 = s << 5;
        #pragma unroll
        for (int t = 0; t < NA; t++) cpa16(dA[t] + s * stgA, gA[t] + k0);
        #pragma unroll
        for (int t = 0; t < 2; t++) cpa16(dB[t] + s * stgB, gB[t] + k0);
        CP_COMMIT();
    }

    for (int it = 0; it < niter; ++it) {
        if (it + 2 < niter) {
            const int s = (it + 2) % NSTAGE;
            const int k0 = (it + 2) << 5;
            #pragma unroll
            for (int t = 0; t < NA; t++) cpa16(dA[t] + s * stgA, gA[t] + k0);
            #pragma unroll
            for (int t = 0; t < 2; t++) cpa16(dB[t] + s * stgB, gB[t] + k0);
            CP_COMMIT();
            CP_WAIT(2);
        } else if (it + 2 == niter) {
            CP_WAIT(1);
        } else {
            CP_WAIT(0);
        }
        __syncthreads();

        const int st = it % NSTAGE;
        const uint32_t aOff = st * stgA, bOff = st * stgB;
        #pragma unroll
        for (int ks = 0; ks < 2; ks++) {
            const uint32_t kadd = ks * 32;
            uint32_t af[2][4];
            ldsm_x4(af[0], aAddr[0] + aOff + kadd);
            ldsm_x4(af[1], aAddr[1] + aOff + kadd);
            #pragma unroll
            for (int nb = 0; nb < NB; nb++) {
                uint32_t bq[4];
                ldsm_x4(bq, bAddr[nb] + bOff + kadd);
                mma_bf16(acc[0][2 * nb    ], af[0], bq[0], bq[1]);
                mma_bf16(acc[1][2 * nb    ], af[1], bq[0], bq[1]);
                mma_bf16(acc[0][2 * nb + 1], af[0], bq[2], bq[3]);
                mma_bf16(acc[1][2 * nb + 1], af[1], bq[2], bq[3]);
            }
        }
        __syncthreads();
    }

    #pragma unroll
    for (int mi = 0; mi < 2; mi++) {
        #pragma unroll
        for (int gg = 0; gg < 2; gg++) {
            int r = row0 + wm * 32 + mi * 16 + g + gg * 8;
            #pragma unroll
            for (int ni = 0; ni < NI; ni++) {
                int c = col0 + wn * (NI * 8) + ni * 8 + tig * 2;
                float vx = acc[mi][ni][gg * 2 + 0] * scale;
                float vy = acc[mi][ni][gg * 2 + 1] * scale;
                if (bias) { vx += bias[c]; vy += bias[c + 1]; }
                if constexpr (sizeof(OutT) == 2) {
                    __nv_bfloat162 bv = __float22bfloat162_rn(make_float2(vx, vy));
                    *(uint32_t*)((unsigned short*)C + (size_t)r * ldc + c) = *(uint32_t*)&bv;
                } else {
                    float2 v; v.x = vx; v.y = vy;
                    *(float2*)((float*)C + (size_t)r * ldc + c) = v;
                }
            }
        }
    }
}

// ================= fused 12-head logits GEMM + exp + row sums (ldmatrix, 3-stage) =================
__global__ __launch_bounds__(256, 2) void heads_gemm_bf(
    const unsigned short* __restrict__ A,
    const unsigned short* __restrict__ B,
    unsigned short* __restrict__ P,
    float* __restrict__ rsum)
{
    constexpr uint32_t stgA = 128 * HSTR * 4;
    constexpr uint32_t stgB = 128 * HSTR * 4;

    extern __shared__ uint32_t dynsm[];
    const uint32_t sbase = (uint32_t)__cvta_generic_to_shared(dynsm);
    const uint32_t sA = sbase;
    const uint32_t sB = sbase + NSTAGE * stgA;

    const int tid = threadIdx.x;
    const int row0 = blockIdx.y * 128, col0 = blockIdx.x * 128;
    const int wid = tid >> 5, lane = tid & 31;
    const int wm = wid & 3, wn = wid >> 2;
    const int g = lane >> 2, tig = lane & 3;
    const int seg = lane >> 3, l7 = lane & 7;

    const unsigned short* gA[2]; uint32_t dA[2];
    const unsigned short* gB[2]; uint32_t dB[2];
    #pragma unroll
    for (int t = 0; t < 2; t++) {
        int ch = tid + t * 256;
        int cr = ch >> 2, cc = ch & 3;
        gA[t] = A + (size_t)(row0 + cr) * DIM + cc * 8;
        dA[t] = sA + cr * 80 + cc * 16;
        gB[t] = B + (size_t)(col0 + cr) * DIM + cc * 8;
        dB[t] = sB + cr * 80 + cc * 16;
    }

    const int rowA = (seg & 1) * 8 + l7;
    const uint32_t kAb = (seg >> 1) * 16;
    uint32_t aAddr[2];
    #pragma unroll
    for (int mi = 0; mi < 2; mi++)
        aAddr[mi] = sA + (uint32_t)(wm * 32 + mi * 16 + rowA) * 80 + kAb;
    const int rowB = (seg >> 1) * 8 + l7;
    const uint32_t kBb = (seg & 1) * 16;
    uint32_t bAddr[4];
    #pragma unroll
    for (int nb = 0; nb < 4; nb++)
        bAddr[nb] = sB + (uint32_t)(wn * 64 + nb * 16 + rowB) * 80 + kBb;

    const int niter = DIM >> 5;  // 24

    #pragma unroll
    for (int s = 0; s < 2; s++) {
        const int k0 = s << 5;
        #pragma unroll
        for (int t = 0; t < 2; t++) {
            cpa16(dA[t] + s * stgA, gA[t] + k0);
            cpa16(dB[t] + s * stgB, gB[t] + k0);
        }
        CP_COMMIT();
    }

    for (int h = 0; h < NHEAD; h++) {
        float acc[2][8][4];
        #pragma unroll
        for (int i = 0; i < 2; i++)
            #pragma unroll
            for (int j = 0; j < 8; j++)
                #pragma unroll
                for (int q = 0; q < 4; q++) acc[i][j][q] = 0.f;

        #pragma unroll
        for (int ki = 0; ki < 2; ki++) {
            const int it = h * 2 + ki;
            if (it + 2 < niter) {
                const int s = (it + 2) % NSTAGE;
                const int k0 = (it + 2) << 5;
                #pragma unroll
                for (int t = 0; t < 2; t++) {
                    cpa16(dA[t] + s * stgA, gA[t] + k0);
                    cpa16(dB[t] + s * stgB, gB[t] + k0);
                }
                CP_COMMIT();
                CP_WAIT(2);
            } else if (it + 2 == niter) {
                CP_WAIT(1);
            } else {
                CP_WAIT(0);
            }
            __syncthreads();

            const int st = it % NSTAGE;
            const uint32_t aOff = st * stgA, bOff = st * stgB;
            #pragma unroll
            for (int ks = 0; ks < 2; ks++) {
                const uint32_t kadd = ks * 32;
                uint32_t af[2][4];
                ldsm_x4(af[0], aAddr[0] + aOff + kadd);
                ldsm_x4(af[1], aAddr[1] + aOff + kadd);
                #pragma unroll
                for (int nb = 0; nb < 4; nb++) {
                    uint32_t bq[4];
                    ldsm_x4(bq, bAddr[nb] + bOff + kadd);
                    mma_bf16(acc[0][2 * nb    ], af[0], bq[0], bq[1]);
                    mma_bf16(acc[1][2 * nb    ], af[1], bq[0], bq[1]);
                    mma_bf16(acc[0][2 * nb + 1], af[0], bq[2], bq[3]);
                    mma_bf16(acc[1][2 * nb + 1], af[1], bq[2], bq[3]);
                }
            }
            __syncthreads();
        }

        __half* plane = (__half*)P + (size_t)h * NTOK * NTOK;
        float* rs_h = rsum + h * NTOK;
        #pragma unroll
        for (int mi = 0; mi < 2; mi++) {
            #pragma unroll
            for (int gg = 0; gg < 2; gg++) {
                int r = row0 + wm * 32 + mi * 16 + g + gg * 8;
                float rowacc = 0.f;
                #pragma unroll
                for (int ni = 0; ni < 8; ni++) {
                    int c = col0 + wn * 64 + ni * 8 + tig * 2;
                    float e0 = __expf(0.125f * acc[mi][ni][gg * 2 + 0]);
                    float e1 = __expf(0.125f * acc[mi][ni][gg * 2 + 1]);
                    *(__half2*)(plane + (size_t)r * NTOK + c) = __floats2half2_rn(e0, e1);
                    rowacc += e0 + e1;
                }
                rowacc += __shfl_xor_sync(0xffffffffu, rowacc, 1);
                rowacc += __shfl_xor_sync(0xffffffffu, rowacc, 2);
                if (tig == 0) atomicAdd(&rs_h[r], rowacc);
            }
        }
    }
}

// ================= V transpose (bf16) =================
__global__ void transpose_v(const unsigned short* __restrict__ V, unsigned short* __restrict__ Vt)
{
    __shared__ unsigned short t[32][34];
    int x = blockIdx.x * 32 + threadIdx.x;
    int y0 = blockIdx.y * 32;
    for (int dy = threadIdx.y; dy < 32; dy += 8)
        t[dy][threadIdx.x] = V[(size_t)(y0 + dy) * DIM + x];
    __syncthreads();
    int xo = blockIdx.y * 32 + threadIdx.x;
    int yo0 = blockIdx.x * 32;
    for (int dy = threadIdx.y; dy < 32; dy += 8)
        Vt[(size_t)(yo0 + dy) * NTOK + xo] = t[threadIdx.x][dy];
}

// ================= zero rsum + stats =================
__global__ void zero_kernel(float* __restrict__ rsum)
{
    int i = blockIdx.x * blockDim.x + threadIdx.x;
    if (i < NHEAD * NTOK) rsum[i] = 0.f;
    if (i == 0) { g_stats[0] = 0.0; g_stats[1] = 0.0; }
}

// ================= combine: Wa avg + Gaussian + stats (384 thr, 16B loads) =================
__global__ __launch_bounds__(384) void wf_combine_kernel(
    const float* __restrict__ dd, const float* __restrict__ rsum)
{
    __shared__ float shInv[NHEAD];
    __shared__ float redA[12], redB[12];
    const int i = blockIdx.x, tid = threadIdx.x;
    const int lane = tid & 31, wid = tid >> 5;
    const int NP8 = NTOK / 8;                       // 384 uint4 per row
    const size_t PL8 = (size_t)NTOK * NTOK / 8;
    const uint4* planes = (const uint4*)g_Shx;
    const size_t rowoff = (size_t)i * NP8;

    if (tid < NHEAD) shInv[tid] = 1.f / (rsum[tid * NTOK + i] * (float)NHEAD);
    __syncthreads();

    float iz[NHEAD];
    #pragma unroll
    for (int h = 0; h < NHEAD; h++) iz[h] = shInv[h];

    const float4* drow = (const float4*)(dd + (size_t)i * NTOK);
    float4* frow = (float4*)(g_Wf + (size_t)i * NTOK);
    float s1 = 0.f, s2 = 0.f;

    const int j = tid;  // exactly one uint4 per thread
    {
        float wa[8];
        #pragma unroll
        for (int q = 0; q < 8; q++) wa[q] = 0.f;
        #pragma unroll
        for (int h = 0; h < NHEAD; h++) {
            uint4 u = planes[h * PL8 + rowoff + j];
            float2 e0 = __half22float2(*(__half2*)&u.x);
            float2 e1 = __half22float2(*(__half2*)&u.y);
            float2 e2 = __half22float2(*(__half2*)&u.z);
            float2 e3 = __half22float2(*(__half2*)&u.w);
            wa[0] += e0.x * iz[h]; wa[1] += e0.y * iz[h];
            wa[2] += e1.x * iz[h]; wa[3] += e1.y * iz[h];
            wa[4] += e2.x * iz[h]; wa[5] += e2.y * iz[h];
            wa[6] += e3.x * iz[h]; wa[7] += e3.y * iz[h];
        }
        float4 d0 = drow[j * 2], d1 = drow[j * 2 + 1];
        float df[8] = {d0.x, d0.y, d0.z, d0.w, d1.x, d1.y, d1.z, d1.w};
        float wf[8];
        #pragma unroll
        for (int q = 0; q < 8; q++) {
            wf[q] = __expf(-0.5f * df[q] * df[q]) * wa[q];
            s1 += wf[q];
            s2 += wf[q] * wf[q];
        }
        float4 w0, w1;
        w0.x = wf[0]; w0.y = wf[1]; w0.z = wf[2]; w0.w = wf[3];
        w1.x = wf[4]; w1.y = wf[5]; w1.z = wf[6]; w1.w = wf[7];
        frow[j * 2] = w0;
        frow[j * 2 + 1] = w1;
    }

    s1 = warp_sum(s1);
    s2 = warp_sum(s2);
    if (lane == 0) { redA[wid] = s1; redB[wid] = s2; }
    __syncthreads();
    if (wid == 0) {
        float a = (lane < 12) ? redA[lane] : 0.f;
        float b = (lane < 12) ? redB[lane] : 0.f;
        a = warp_sum(a);
        b = warp_sum(b);
        if (lane == 0) {
            atomicAdd(&g_stats[0], (double)a);
            atomicAdd(&g_stats[1], (double)b);
        }
    }
}

// ================= masked softmax (no shift) -> bf16 attn =================
__global__ __launch_bounds__(256) void masked_softmax_kernel()
{
    __shared__ float4 z[NTOK / 4];
    __shared__ float redB[8];
    __shared__ float sh_thr;
    const int i = blockIdx.x, tid = threadIdx.x;
    const int lane = tid & 31, wid = tid >> 5;
    const int NP4 = NTOK / 4;

    if (tid == 0) {
        double cnt = (double)NTOK * (double)NTOK;
        double mean = g_stats[0] / cnt;
        double var = (g_stats[1] - g_stats[0] * g_stats[0] / cnt) / (cnt - 1.0);
        if (var < 0.0) var = 0.0;
        sh_thr = (float)(mean + 0.5 * sqrt(var));
    }
    __syncthreads();
    const float thr = sh_thr;
    const float invthr = 1.f / thr;

    const float4* srow = (const float4*)(g_S + (size_t)i * NTOK);
    const float4* frow = (const float4*)(g_Wf + (size_t)i * NTOK);

    float lsum = 0.f;
    #pragma unroll
    for (int t = 0; t < 3; t++) {
        int j = tid + t * 256;
        float4 wf = frow[j];
        float4 s = srow[j];
        float w0 = (wf.x < thr) ? wf.x * invthr : 1.f;
        float w1 = (wf.y < thr) ? wf.y * invthr : 1.f;
        float w2 = (wf.z < thr) ? wf.z * invthr : 1.f;
        float w3 = (wf.w < thr) ? wf.w * invthr : 1.f;
        float4 e;
        e.x = __expf(s.x * w0);
        e.y = __expf(s.y * w1);
        e.z = __expf(s.z * w2);
        e.w = __expf(s.w * w3);
        z[j] = e;
        lsum += e.x + e.y + e.z + e.w;
    }
    lsum = warp_sum(lsum);
    if (lane == 0) redB[wid] = lsum;
    __syncthreads();
    if (wid == 0) {
        float t = (lane < 8) ? redB[lane] : 0.f;
        t = warp_sum(t);
        if (lane == 0) redB[0] = t;
    }
    __syncthreads();
    const float invs = 1.f / redB[0];

    uint2* arow = (uint2*)((unsigned short*)g_Att + (size_t)i * NTOK);
    #pragma unroll
    for (int t = 0; t < 3; t++) {
        int j = tid + t * 256;
        float4 e = z[j];
        __nv_bfloat162 b0 = __float22bfloat162_rn(make_float2(e.x * invs, e.y * invs));
        __nv_bfloat162 b1 = __float22bfloat162_rn(make_float2(e.z * invs, e.w * invs));
        uint2 u; u.x = *(uint32_t*)&b0; u.y = *(uint32_t*)&b1;
        arow[j] = u;
    }
}

// ================= residual + LayerNorm =================
__global__ __launch_bounds__(256) void ln_kernel(
    const float* __restrict__ hs,
    const float* __restrict__ gamma,
    const float* __restrict__ beta,
    float* __restrict__ out)
{
    const int i = blockIdx.x, tid = threadIdx.x;
    const int lane = tid & 31, wid = tid >> 5;
    __shared__ float r1[8], r2[8];

    const float* orow = g_O + (size_t)i * DIM;
    const float* srow = hs + (size_t)i * DIM;

    float x[3];
    float s = 0.f, ss = 0.f;
    #pragma unroll
    for (int t = 0; t < 3; t++) {
        int c = tid + t * 256;
        x[t] = srow[c] + orow[c];
        s += x[t];
        ss += x[t] * x[t];
    }
    s = warp_sum(s);
    ss = warp_sum(ss);
    if (lane == 0) { r1[wid] = s; r2[wid] = ss; }
    __syncthreads();
    if (wid == 0) {
        float a = (lane < 8) ? r1[lane] : 0.f;
        float b = (lane < 8) ? r2[lane] : 0.f;
        a = warp_sum(a);
        b = warp_sum(b);
        if (lane == 0) { r1[0] = a; r2[0] = b; }
    }
    __syncthreads();
    const float mu = r1[0] * (1.f / DIM);
    const float var = r2[0] * (1.f / DIM) - mu * mu;
    const float inv = rsqrtf(var + 1e-5f);

    #pragma unroll
    for (int t = 0; t < 3; t++) {
        int c = tid + t * 256;
        out[(size_t)i * DIM + c] = (x[t] - mu) * inv * gamma[c] + beta[c];
    }
}

// ================= host =================
extern "C" void kernel_launch(void* const* d_in, const int* in_sizes, int n_in,
                              void* d_out, int out_size)
{
    const float* h_a  = (const float*)d_in[0];
    const float* h_s  = (const float*)d_in[1];
    const float* dep  = (const float*)d_in[2];
    const float* Wq_a = (const float*)d_in[3];
    const float* bq_a = (const float*)d_in[4];
    const float* Wk_a = (const float*)d_in[5];
    const float* bk_a = (const float*)d_in[6];
    const float* Wq   = (const float*)d_in[7];
    const float* bq   = (const float*)d_in[8];
    const float* Wk   = (const float*)d_in[9];
    const float* bk   = (const float*)d_in[10];
    const float* Wv   = (const float*)d_in[11];
    const float* bv   = (const float*)d_in[12];
    const float* lng  = (const float*)d_in[13];
    const float* lnb  = (const float*)d_in[14];
    float* out = (float*)d_out;

    unsigned short *hab, *hsb, *Wqab, *Wkab, *Wqb, *Wkb, *Wvb;
    unsigned short *qab, *kab, *Qb, *Kb, *Vb, *Vt, *Att, *Shx;
    float *O, *S, *Wf, *rsum;
    cudaGetSymbolAddress((void**)&hab,  g_hab);
    cudaGetSymbolAddress((void**)&hsb,  g_hsb);
    cudaGetSymbolAddress((void**)&Wqab, g_Wqab);
    cudaGetSymbolAddress((void**)&Wkab, g_Wkab);
    cudaGetSymbolAddress((void**)&Wqb,  g_Wqb);
    cudaGetSymbolAddress((void**)&Wkb,  g_Wkb);
    cudaGetSymbolAddress((void**)&Wvb,  g_Wvb);
    cudaGetSymbolAddress((void**)&qab,  g_qab);
    cudaGetSymbolAddress((void**)&kab,  g_kab);
    cudaGetSymbolAddress((void**)&Qb,   g_Qb);
    cudaGetSymbolAddress((void**)&Kb,   g_Kb);
    cudaGetSymbolAddress((void**)&Vb,   g_Vb);
    cudaGetSymbolAddress((void**)&Vt,   g_Vt);
    cudaGetSymbolAddress((void**)&Att,  g_Att);
    cudaGetSymbolAddress((void**)&Shx,  g_Shx);
    cudaGetSymbolAddress((void**)&O,    g_O);
    cudaGetSymbolAddress((void**)&S,    g_S);
    cudaGetSymbolAddress((void**)&Wf,   g_Wf);
    cudaGetSymbolAddress((void**)&rsum, g_rsum);

    const int SM128 = NSTAGE * (128 * HSTR * 4) * 2;       // 61440
    const int SM64  = NSTAGE * (64 * HSTR * 4 + 128 * HSTR * 4);  // 46080

    static cudaStream_t s1;
    static cudaEvent_t e0, e1;
    static int inited = 0;
    if (!inited) {
        cudaStreamCreateWithFlags(&s1, cudaStreamNonBlocking);
        cudaEventCreateWithFlags(&e0, cudaEventDisableTiming);
        cudaEventCreateWithFlags(&e1, cudaEventDisableTiming);
        cudaFuncSetAttribute(gemm_nt_bf<128, unsigned short>,
                             cudaFuncAttributeMaxDynamicSharedMemorySize, SM128);
        cudaFuncSetAttribute(gemm_nt_bf<128, float>,
                             cudaFuncAttributeMaxDynamicSharedMemorySize, SM128);
        cudaFuncSetAttribute(gemm_nt_bf<64, float>,
                             cudaFuncAttributeMaxDynamicSharedMemorySize, SM64);
        cudaFuncSetAttribute(heads_gemm_bf,
                             cudaFuncAttributeMaxDynamicSharedMemorySize, SM128);
        inited = 1;
    }

    const dim3 blk(256);
    const dim3 gProj(DIM / 128, NTOK / 128);    // 6 x 24
    const dim3 gNN(NTOK / 128, NTOK / 128);     // 24 x 24
    const dim3 gAV(DIM / 128, NTOK / 64);       // 6 x 48
    const int NH4 = (NTOK * DIM) / 4;
    const int NW4 = (DIM * DIM) / 4;

    cudaEventRecord(e0, 0);
    cudaStreamWaitEvent(s1, e0, 0);

    // ---- chain A (s1): structural attention weights ----
    zero_kernel<<<(NHEAD * NTOK + 255) / 256, 256, 0, s1>>>(rsum);
    f2b_multi<<<(NH4 + 2 * NW4 + 255) / 256, 256, 0, s1>>>(
        (const float4*)h_a, (uint2*)hab, NH4,
        (const float4*)Wq_a, (uint2*)Wqab, NW4,
        (const float4*)Wk_a, (uint2*)Wkab, NW4,
        nullptr, nullptr, 0);
    gemm_nt_bf<128, unsigned short><<<gProj, blk, SM128, s1>>>(hab, DIM, Wqab, DIM, qab, DIM, DIM, bq_a, 1.f);
    gemm_nt_bf<128, unsigned short><<<gProj, blk, SM128, s1>>>(hab, DIM, Wkab, DIM, kab, DIM, DIM, bk_a, 1.f);
    heads_gemm_bf<<<gNN, blk, SM128, s1>>>(qab, kab, Shx, rsum);
    wf_combine_kernel<<<NTOK, 384, 0, s1>>>(dep, rsum);
    cudaEventRecord(e1, s1);

    // ---- chain B (default): guided attention ----
    f2b_multi<<<(NH4 + 3 * NW4 + 255) / 256, 256>>>(
        (const float4*)h_s, (uint2*)hsb, NH4,
        (const float4*)Wq, (uint2*)Wqb, NW4,
        (const float4*)Wk, (uint2*)Wkb, NW4,
        (const float4*)Wv, (uint2*)Wvb, NW4);
    gemm_nt_bf<128, unsigned short><<<gProj, blk, SM128>>>(hsb, DIM, Wqb, DIM, Qb, DIM, DIM, bq, 1.f);
    gemm_nt_bf<128, unsigned short><<<gProj, blk, SM128>>>(hsb, DIM, Wkb, DIM, Kb, DIM, DIM, bk, 1.f);
    gemm_nt_bf<128, unsigned short><<<gProj, blk, SM128>>>(hsb, DIM, Wvb, DIM, Vb, DIM, DIM, bv, 1.f);
    transpose_v<<<dim3(DIM / 32, NTOK / 32), dim3(32, 8)>>>(Vb, Vt);
    const float score_scale = 1.f / sqrtf((float)DIM);
    gemm_nt_bf<128, float><<<gNN, blk, SM128>>>(Qb, DIM, Kb, DIM, S, NTOK, DIM, nullptr, score_scale);

    // join, then tail
    cudaStreamWaitEvent(0, e1, 0);
    masked_softmax_kernel<<<NTOK, 256>>>();
    gemm_nt_bf<64, float><<<gAV, blk, SM64>>>(Att, NTOK, Vt, NTOK, O, DIM, NTOK, nullptr, 1.f);
    ln_kernel<<<NTOK, 256>>>(h_s, lng, lnb, out);
}

// round 9
// speedup vs baseline: 4.4622x; 1.0205x over previous
#include <cuda_runtime.h>
#include <cuda_fp16.h>
#include <cuda_bf16.h>
#include <math.h>
#include <stdint.h>

#define NTOK 3072
#define DIM  768
#define NHEAD 12
#define HDIM 64

// ---------------- static device scratch ----------------
__device__ unsigned short g_hab[NTOK * DIM];
__device__ unsigned short g_hsb[NTOK * DIM];
__device__ unsigned short g_Wqab[DIM * DIM];
__device__ unsigned short g_Wkab[DIM * DIM];
__device__ unsigned short g_Wqb [DIM * DIM];
__device__ unsigned short g_Wkb [DIM * DIM];
__device__ unsigned short g_Wvb [DIM * DIM];
__device__ unsigned short g_qab[NTOK * DIM];
__device__ unsigned short g_kab[NTOK * DIM];
__device__ unsigned short g_Qb [NTOK * DIM];
__device__ unsigned short g_Kb [NTOK * DIM];
__device__ unsigned short g_Vb [NTOK * DIM];
__device__ unsigned short g_Vt [DIM * NTOK];
__device__ float g_O [NTOK * DIM];
__device__ float g_S [(size_t)NTOK * NTOK];
__device__ unsigned short g_Att[(size_t)NTOK * NTOK];
__device__ unsigned short g_Shx[(size_t)NHEAD * NTOK * NTOK]; // fp16 exp planes
__device__ float g_Wf[(size_t)NTOK * NTOK];
__device__ float g_rsum[NHEAD * NTOK];
__device__ double g_stats[2];

// ---------------- helpers ----------------
__device__ __forceinline__ float warp_sum(float v) {
    #pragma unroll
    for (int o = 16; o; o >>= 1) v += __shfl_xor_sync(0xffffffffu, v, o);
    return v;
}
__device__ __forceinline__ void mma_bf16(float* d, const uint32_t* a, uint32_t b0, uint32_t b1) {
    asm volatile(
        "mma.sync.aligned.m16n8k16.row.col.f32.bf16.bf16.f32 "
        "{%0,%1,%2,%3}, {%4,%5,%6,%7}, {%8,%9}, {%0,%1,%2,%3};\n"
        : "+f"(d[0]), "+f"(d[1]), "+f"(d[2]), "+f"(d[3])
        : "r"(a[0]), "r"(a[1]), "r"(a[2]), "r"(a[3]), "r"(b0), "r"(b1));
}
__device__ __forceinline__ void ldsm_x4(uint32_t* r, uint32_t addr) {
    asm volatile("ldmatrix.sync.aligned.m8n8.x4.shared.b16 {%0,%1,%2,%3}, [%4];"
        : "=r"(r[0]), "=r"(r[1]), "=r"(r[2]), "=r"(r[3]) : "r"(addr));
}
__device__ __forceinline__ void cpa16(uint32_t smem, const void* gptr) {
    asm volatile("cp.async.ca.shared.global [%0], [%1], 16;\n" :: "r"(smem), "l"(gptr));
}
#define CP_COMMIT()  asm volatile("cp.async.commit_group;\n")
#define CP_WAIT(N)   asm volatile("cp.async.wait_group %0;\n" :: "n"(N))

#define RSTR 144        // bytes per smem row (128 data + 16 pad); banks 4r mod 32: conflict-free
#define NSTAGE 3

// ---------------- fp32 -> bf16 conversion, multi-array fused ----------------
__global__ void f2b_multi(const float4* a0, uint2* o0, int n0,
                          const float4* a1, uint2* o1, int n1,
                          const float4* a2, uint2* o2, int n2,
                          const float4* a3, uint2* o3, int n3)
{
    int i = blockIdx.x * blockDim.x + threadIdx.x;
    const float4* in; uint2* out; int idx;
    if (i < n0) { in = a0; out = o0; idx = i; }
    else if (i < n0 + n1) { in = a1; out = o1; idx = i - n0; }
    else if (i < n0 + n1 + n2) { in = a2; out = o2; idx = i - n0 - n1; }
    else if (i < n0 + n1 + n2 + n3) { in = a3; out = o3; idx = i - n0 - n1 - n2; }
    else return;
    float4 v = in[idx];
    __nv_bfloat162 a = __float22bfloat162_rn(make_float2(v.x, v.y));
    __nv_bfloat162 b = __float22bfloat162_rn(make_float2(v.z, v.w));
    uint2 u; u.x = *(uint32_t*)&a; u.y = *(uint32_t*)&b;
    out[idx] = u;
}

// ================= bf16 TC NT GEMM (ldmatrix, BK=64, 3-stage): C = scale*A.B^T (+bias) =================
template <int BM, typename OutT>
__global__ __launch_bounds__(256, 2) void gemm_nt_bf(
    const unsigned short* __restrict__ A, int lda,
    const unsigned short* __restrict__ B, int ldb,
    OutT* __restrict__ C, int ldc, int K,
    const float* __restrict__ bias, float scale)
{
    constexpr int WMN = BM / 32;
    constexpr int WNN = 8 / WMN;
    constexpr int NI  = 128 / (WNN * 8);
    constexpr int NB  = NI / 2;
    constexpr int CA  = BM / 32;         // A 16B-chunks per thread (8 per row)
    constexpr int CB  = 4;               // B chunks per thread
    constexpr uint32_t stgA = BM * RSTR;
    constexpr uint32_t stgB = 128 * RSTR;

    extern __shared__ uint32_t dynsm[];
    const uint32_t sbase = (uint32_t)__cvta_generic_to_shared(dynsm);
    const uint32_t sA = sbase;
    const uint32_t sB = sbase + NSTAGE * stgA;

    const int tid = threadIdx.x;
    const int row0 = blockIdx.y * BM, col0 = blockIdx.x * 128;
    const int wid = tid >> 5, lane = tid & 31;
    const int wm = wid % WMN, wn = wid / WMN;
    const int g = lane >> 2, tig = lane & 3;
    const int seg = lane >> 3, l7 = lane & 7;

    float acc[2][NI][4];
    #pragma unroll
    for (int i = 0; i < 2; i++)
        #pragma unroll
        for (int j = 0; j < NI; j++)
            #pragma unroll
            for (int q = 0; q < 4; q++) acc[i][j][q] = 0.f;

    const unsigned short* gA[CA]; uint32_t dA[CA];
    #pragma unroll
    for (int t = 0; t < CA; t++) {
        int ch = tid + t * 256;
        int r = ch >> 3, c16 = ch & 7;
        gA[t] = A + (size_t)(row0 + r) * lda + c16 * 8;
        dA[t] = sA + r * RSTR + c16 * 16;
    }
    const unsigned short* gB[CB]; uint32_t dB[CB];
    #pragma unroll
    for (int t = 0; t < CB; t++) {
        int ch = tid + t * 256;
        int r = ch >> 3, c16 = ch & 7;
        gB[t] = B + (size_t)(col0 + r) * ldb + c16 * 8;
        dB[t] = sB + r * RSTR + c16 * 16;
    }

    const int rowA = (seg & 1) * 8 + l7;
    const uint32_t kAb = (seg >> 1) * 16;
    uint32_t aAddr[2];
    #pragma unroll
    for (int mi = 0; mi < 2; mi++)
        aAddr[mi] = sA + (uint32_t)(wm * 32 + mi * 16 + rowA) * RSTR + kAb;
    const int rowB = (seg >> 1) * 8 + l7;
    const uint32_t kBb = (seg & 1) * 16;
    uint32_t bAddr[NB];
    #pragma unroll
    for (int nb = 0; nb < NB; nb++)
        bAddr[nb] = sB + (uint32_t)(wn * (NI * 8) + nb * 16 + rowB) * RSTR + kBb;

    const int niter = K >> 6;   // BK = 64 halves

    #pragma unroll
    for (int s = 0; s < 2; s++) {
        const int k0 = s << 6;
        #pragma unroll
        for (int t = 0; t < CA; t++) cpa16(dA[t] + s * stgA, gA[t] + k0);
        #pragma unroll
        for (int t = 0; t < CB; t++) cpa16(dB[t] + s * stgB, gB[t] + k0);
        CP_COMMIT();
    }

    for (int it = 0; it < niter; ++it) {
        if (it + 2 < niter) {
            const int s = (it + 2) % NSTAGE;
            const int k0 = (it + 2) << 6;
            #pragma unroll
            for (int t = 0; t < CA; t++) cpa16(dA[t] + s * stgA, gA[t] + k0);
            #pragma unroll
            for (int t = 0; t < CB; t++) cpa16(dB[t] + s * stgB, gB[t] + k0);
            CP_COMMIT();
            CP_WAIT(2);
        } else if (it + 2 == niter) {
            CP_WAIT(1);
        } else {
            CP_WAIT(0);
        }
        __syncthreads();

        const int st = it % NSTAGE;
        const uint32_t aOff = st * stgA, bOff = st * stgB;
        #pragma unroll
        for (int ks = 0; ks < 4; ks++) {
            const uint32_t kadd = ks * 32;
            uint32_t af[2][4];
            ldsm_x4(af[0], aAddr[0] + aOff + kadd);
            ldsm_x4(af[1], aAddr[1] + aOff + kadd);
            #pragma unroll
            for (int nb = 0; nb < NB; nb++) {
                uint32_t bq[4];
                ldsm_x4(bq, bAddr[nb] + bOff + kadd);
                mma_bf16(acc[0][2 * nb    ], af[0], bq[0], bq[1]);
                mma_bf16(acc[1][2 * nb    ], af[1], bq[0], bq[1]);
                mma_bf16(acc[0][2 * nb + 1], af[0], bq[2], bq[3]);
                mma_bf16(acc[1][2 * nb + 1], af[1], bq[2], bq[3]);
            }
        }
        __syncthreads();
    }

    #pragma unroll
    for (int mi = 0; mi < 2; mi++) {
        #pragma unroll
        for (int gg = 0; gg < 2; gg++) {
            int r = row0 + wm * 32 + mi * 16 + g + gg * 8;
            #pragma unroll
            for (int ni = 0; ni < NI; ni++) {
                int c = col0 + wn * (NI * 8) + ni * 8 + tig * 2;
                float vx = acc[mi][ni][gg * 2 + 0] * scale;
                float vy = acc[mi][ni][gg * 2 + 1] * scale;
                if (bias) { vx += bias[c]; vy += bias[c + 1]; }
                if constexpr (sizeof(OutT) == 2) {
                    __nv_bfloat162 bv = __float22bfloat162_rn(make_float2(vx, vy));
                    *(uint32_t*)((unsigned short*)C + (size_t)r * ldc + c) = *(uint32_t*)&bv;
                } else {
                    float2 v; v.x = vx; v.y = vy;
                    *(float2*)((float*)C + (size_t)r * ldc + c) = v;
                }
            }
        }
    }
}

// ================= fused 12-head logits GEMM (BK=64: 1 stage per head) =================
__global__ __launch_bounds__(256, 2) void heads_gemm_bf(
    const unsigned short* __restrict__ A,
    const unsigned short* __restrict__ B,
    unsigned short* __restrict__ P,
    float* __restrict__ rsum)
{
    constexpr uint32_t stgA = 128 * RSTR;
    constexpr uint32_t stgB = 128 * RSTR;

    extern __shared__ uint32_t dynsm[];
    const uint32_t sbase = (uint32_t)__cvta_generic_to_shared(dynsm);
    const uint32_t sA = sbase;
    const uint32_t sB = sbase + NSTAGE * stgA;

    const int tid = threadIdx.x;
    const int row0 = blockIdx.y * 128, col0 = blockIdx.x * 128;
    const int wid = tid >> 5, lane = tid & 31;
    const int wm = wid & 3, wn = wid >> 2;
    const int g = lane >> 2, tig = lane & 3;
    const int seg = lane >> 3, l7 = lane & 7;

    const unsigned short* gA[4]; uint32_t dA[4];
    const unsigned short* gB[4]; uint32_t dB[4];
    #pragma unroll
    for (int t = 0; t < 4; t++) {
        int ch = tid + t * 256;
        int r = ch >> 3, c16 = ch & 7;
        gA[t] = A + (size_t)(row0 + r) * DIM + c16 * 8;
        dA[t] = sA + r * RSTR + c16 * 16;
        gB[t] = B + (size_t)(col0 + r) * DIM + c16 * 8;
        dB[t] = sB + r * RSTR + c16 * 16;
    }

    const int rowA = (seg & 1) * 8 + l7;
    const uint32_t kAb = (seg >> 1) * 16;
    uint32_t aAddr[2];
    #pragma unroll
    for (int mi = 0; mi < 2; mi++)
        aAddr[mi] = sA + (uint32_t)(wm * 32 + mi * 16 + rowA) * RSTR + kAb;
    const int rowB = (seg >> 1) * 8 + l7;
    const uint32_t kBb = (seg & 1) * 16;
    uint32_t bAddr[4];
    #pragma unroll
    for (int nb = 0; nb < 4; nb++)
        bAddr[nb] = sB + (uint32_t)(wn * 64 + nb * 16 + rowB) * RSTR + kBb;

    // one K=64 stage per head
    #pragma unroll
    for (int s = 0; s < 2; s++) {
        const int k0 = s << 6;
        #pragma unroll
        for (int t = 0; t < 4; t++) {
            cpa16(dA[t] + s * stgA, gA[t] + k0);
            cpa16(dB[t] + s * stgB, gB[t] + k0);
        }
        CP_COMMIT();
    }

    for (int h = 0; h < NHEAD; h++) {
        if (h + 2 < NHEAD) {
            const int s = (h + 2) % NSTAGE;
            const int k0 = (h + 2) << 6;
            #pragma unroll
            for (int t = 0; t < 4; t++) {
                cpa16(dA[t] + s * stgA, gA[t] + k0);
                cpa16(dB[t] + s * stgB, gB[t] + k0);
            }
            CP_COMMIT();
            CP_WAIT(2);
        } else if (h + 2 == NHEAD) {
            CP_WAIT(1);
        } else {
            CP_WAIT(0);
        }
        __syncthreads();

        float acc[2][8][4];
        #pragma unroll
        for (int i = 0; i < 2; i++)
            #pragma unroll
            for (int j = 0; j < 8; j++)
                #pragma unroll
                for (int q = 0; q < 4; q++) acc[i][j][q] = 0.f;

        const int st = h % NSTAGE;
        const uint32_t aOff = st * stgA, bOff = st * stgB;
        #pragma unroll
        for (int ks = 0; ks < 4; ks++) {
            const uint32_t kadd = ks * 32;
            uint32_t af[2][4];
            ldsm_x4(af[0], aAddr[0] + aOff + kadd);
            ldsm_x4(af[1], aAddr[1] + aOff + kadd);
            #pragma unroll
            for (int nb = 0; nb < 4; nb++) {
                uint32_t bq[4];
                ldsm_x4(bq, bAddr[nb] + bOff + kadd);
                mma_bf16(acc[0][2 * nb    ], af[0], bq[0], bq[1]);
                mma_bf16(acc[1][2 * nb    ], af[1], bq[0], bq[1]);
                mma_bf16(acc[0][2 * nb + 1], af[0], bq[2], bq[3]);
                mma_bf16(acc[1][2 * nb + 1], af[1], bq[2], bq[3]);
            }
        }
        __syncthreads();

        // epilogue: exp(logit/8) -> fp16 plane + row-sum atomics (overlaps next head's loads)
        __half* plane = (__half*)P + (size_t)h * NTOK * NTOK;
        float* rs_h = rsum + h * NTOK;
        #pragma unroll
        for (int mi = 0; mi < 2; mi++) {
            #pragma unroll
            for (int gg = 0; gg < 2; gg++) {
                int r = row0 + wm * 32 + mi * 16 + g + gg * 8;
                float rowacc = 0.f;
                #pragma unroll
                for (int ni = 0; ni < 8; ni++) {
                    int c = col0 + wn * 64 + ni * 8 + tig * 2;
                    float e0 = __expf(0.125f * acc[mi][ni][gg * 2 + 0]);
                    float e1 = __expf(0.125f * acc[mi][ni][gg * 2 + 1]);
                    *(__half2*)(plane + (size_t)r * NTOK + c) = __floats2half2_rn(e0, e1);
                    rowacc += e0 + e1;
                }
                rowacc += __shfl_xor_sync(0xffffffffu, rowacc, 1);
                rowacc += __shfl_xor_sync(0xffffffffu, rowacc, 2);
                if (tig == 0) atomicAdd(&rs_h[r], rowacc);
            }
        }
    }
}

// ================= V transpose (bf16) =================
__global__ void transpose_v(const unsigned short* __restrict__ V, unsigned short* __restrict__ Vt)
{
    __shared__ unsigned short t[32][34];
    int x = blockIdx.x * 32 + threadIdx.x;
    int y0 = blockIdx.y * 32;
    for (int dy = threadIdx.y; dy < 32; dy += 8)
        t[dy][threadIdx.x] = V[(size_t)(y0 + dy) * DIM + x];
    __syncthreads();
    int xo = blockIdx.y * 32 + threadIdx.x;
    int yo0 = blockIdx.x * 32;
    for (int dy = threadIdx.y; dy < 32; dy += 8)
        Vt[(size_t)(yo0 + dy) * NTOK + xo] = t[threadIdx.x][dy];
}

// ================= zero rsum + stats =================
__global__ void zero_kernel(float* __restrict__ rsum)
{
    int i = blockIdx.x * blockDim.x + threadIdx.x;
    if (i < NHEAD * NTOK) rsum[i] = 0.f;
    if (i == 0) { g_stats[0] = 0.0; g_stats[1] = 0.0; }
}

// ================= combine: Wa avg + Gaussian + stats =================
__global__ __launch_bounds__(384) void wf_combine_kernel(
    const float* __restrict__ dd, const float* __restrict__ rsum)
{
    __shared__ float shInv[NHEAD];
    __shared__ float redA[12], redB[12];
    const int i = blockIdx.x, tid = threadIdx.x;
    const int lane = tid & 31, wid = tid >> 5;
    const int NP8 = NTOK / 8;
    const size_t PL8 = (size_t)NTOK * NTOK / 8;
    const uint4* planes = (const uint4*)g_Shx;
    const size_t rowoff = (size_t)i * NP8;

    if (tid < NHEAD) shInv[tid] = 1.f / (rsum[tid * NTOK + i] * (float)NHEAD);
    __syncthreads();

    float iz[NHEAD];
    #pragma unroll
    for (int h = 0; h < NHEAD; h++) iz[h] = shInv[h];

    const float4* drow = (const float4*)(dd + (size_t)i * NTOK);
    float4* frow = (float4*)(g_Wf + (size_t)i * NTOK);
    float s1 = 0.f, s2 = 0.f;

    const int j = tid;
    {
        float wa[8];
        #pragma unroll
        for (int q = 0; q < 8; q++) wa[q] = 0.f;
        #pragma unroll
        for (int h = 0; h < NHEAD; h++) {
            uint4 u = planes[h * PL8 + rowoff + j];
            float2 e0 = __half22float2(*(__half2*)&u.x);
            float2 e1 = __half22float2(*(__half2*)&u.y);
            float2 e2 = __half22float2(*(__half2*)&u.z);
            float2 e3 = __half22float2(*(__half2*)&u.w);
            wa[0] += e0.x * iz[h]; wa[1] += e0.y * iz[h];
            wa[2] += e1.x * iz[h]; wa[3] += e1.y * iz[h];
            wa[4] += e2.x * iz[h]; wa[5] += e2.y * iz[h];
            wa[6] += e3.x * iz[h]; wa[7] += e3.y * iz[h];
        }
        float4 d0 = drow[j * 2], d1 = drow[j * 2 + 1];
        float df[8] = {d0.x, d0.y, d0.z, d0.w, d1.x, d1.y, d1.z, d1.w};
        float wf[8];
        #pragma unroll
        for (int q = 0; q < 8; q++) {
            wf[q] = __expf(-0.5f * df[q] * df[q]) * wa[q];
            s1 += wf[q];
            s2 += wf[q] * wf[q];
        }
        float4 w0, w1;
        w0.x = wf[0]; w0.y = wf[1]; w0.z = wf[2]; w0.w = wf[3];
        w1.x = wf[4]; w1.y = wf[5]; w1.z = wf[6]; w1.w = wf[7];
        frow[j * 2] = w0;
        frow[j * 2 + 1] = w1;
    }

    s1 = warp_sum(s1);
    s2 = warp_sum(s2);
    if (lane == 0) { redA[wid] = s1; redB[wid] = s2; }
    __syncthreads();
    if (wid == 0) {
        float a = (lane < 12) ? redA[lane] : 0.f;
        float b = (lane < 12) ? redB[lane] : 0.f;
        a = warp_sum(a);
        b = warp_sum(b);
        if (lane == 0) {
            atomicAdd(&g_stats[0], (double)a);
            atomicAdd(&g_stats[1], (double)b);
        }
    }
}

// ================= masked softmax (no shift) -> bf16 attn =================
__global__ __launch_bounds__(256) void masked_softmax_kernel()
{
    __shared__ float4 z[NTOK / 4];
    __shared__ float redB[8];
    __shared__ float sh_thr;
    const int i = blockIdx.x, tid = threadIdx.x;
    const int lane = tid & 31, wid = tid >> 5;

    if (tid == 0) {
        double cnt = (double)NTOK * (double)NTOK;
        double mean = g_stats[0] / cnt;
        double var = (g_stats[1] - g_stats[0] * g_stats[0] / cnt) / (cnt - 1.0);
        if (var < 0.0) var = 0.0;
        sh_thr = (float)(mean + 0.5 * sqrt(var));
    }
    __syncthreads();
    const float thr = sh_thr;
    const float invthr = 1.f / thr;

    const float4* srow = (const float4*)(g_S + (size_t)i * NTOK);
    const float4* frow = (const float4*)(g_Wf + (size_t)i * NTOK);

    float lsum = 0.f;
    #pragma unroll
    for (int t = 0; t < 3; t++) {
        int j = tid + t * 256;
        float4 wf = frow[j];
        float4 s = srow[j];
        float w0 = (wf.x < thr) ? wf.x * invthr : 1.f;
        float w1 = (wf.y < thr) ? wf.y * invthr : 1.f;
        float w2 = (wf.z < thr) ? wf.z * invthr : 1.f;
        float w3 = (wf.w < thr) ? wf.w * invthr : 1.f;
        float4 e;
        e.x = __expf(s.x * w0);
        e.y = __expf(s.y * w1);
        e.z = __expf(s.z * w2);
        e.w = __expf(s.w * w3);
        z[j] = e;
        lsum += e.x + e.y + e.z + e.w;
    }
    lsum = warp_sum(lsum);
    if (lane == 0) redB[wid] = lsum;
    __syncthreads();
    if (wid == 0) {
        float t = (lane < 8) ? redB[lane] : 0.f;
        t = warp_sum(t);
        if (lane == 0) redB[0] = t;
    }
    __syncthreads();
    const float invs = 1.f / redB[0];

    uint2* arow = (uint2*)((unsigned short*)g_Att + (size_t)i * NTOK);
    #pragma unroll
    for (int t = 0; t < 3; t++) {
        int j = tid + t * 256;
        float4 e = z[j];
        __nv_bfloat162 b0 = __float22bfloat162_rn(make_float2(e.x * invs, e.y * invs));
        __nv_bfloat162 b1 = __float22bfloat162_rn(make_float2(e.z * invs, e.w * invs));
        uint2 u; u.x = *(uint32_t*)&b0; u.y = *(uint32_t*)&b1;
        arow[j] = u;
    }
}

// ================= residual + LayerNorm =================
__global__ __launch_bounds__(256) void ln_kernel(
    const float* __restrict__ hs,
    const float* __restrict__ gamma,
    const float* __restrict__ beta,
    float* __restrict__ out)
{
    const int i = blockIdx.x, tid = threadIdx.x;
    const int lane = tid & 31, wid = tid >> 5;
    __shared__ float r1[8], r2[8];

    const float* orow = g_O + (size_t)i * DIM;
    const float* srow = hs + (size_t)i * DIM;

    float x[3];
    float s = 0.f, ss = 0.f;
    #pragma unroll
    for (int t = 0; t < 3; t++) {
        int c = tid + t * 256;
        x[t] = srow[c] + orow[c];
        s += x[t];
        ss += x[t] * x[t];
    }
    s = warp_sum(s);
    ss = warp_sum(ss);
    if (lane == 0) { r1[wid] = s; r2[wid] = ss; }
    __syncthreads();
    if (wid == 0) {
        float a = (lane < 8) ? r1[lane] : 0.f;
        float b = (lane < 8) ? r2[lane] : 0.f;
        a = warp_sum(a);
        b = warp_sum(b);
        if (lane == 0) { r1[0] = a; r2[0] = b; }
    }
    __syncthreads();
    const float mu = r1[0] * (1.f / DIM);
    const float var = r2[0] * (1.f / DIM) - mu * mu;
    const float inv = rsqrtf(var + 1e-5f);

    #pragma unroll
    for (int t = 0; t < 3; t++) {
        int c = tid + t * 256;
        out[(size_t)i * DIM + c] = (x[t] - mu) * inv * gamma[c] + beta[c];
    }
}

// ================= host =================
extern "C" void kernel_launch(void* const* d_in, const int* in_sizes, int n_in,
                              void* d_out, int out_size)
{
    const float* h_a  = (const float*)d_in[0];
    const float* h_s  = (const float*)d_in[1];
    const float* dep  = (const float*)d_in[2];
    const float* Wq_a = (const float*)d_in[3];
    const float* bq_a = (const float*)d_in[4];
    const float* Wk_a = (const float*)d_in[5];
    const float* bk_a = (const float*)d_in[6];
    const float* Wq   = (const float*)d_in[7];
    const float* bq   = (const float*)d_in[8];
    const float* Wk   = (const float*)d_in[9];
    const float* bk   = (const float*)d_in[10];
    const float* Wv   = (const float*)d_in[11];
    const float* bv   = (const float*)d_in[12];
    const float* lng  = (const float*)d_in[13];
    const float* lnb  = (const float*)d_in[14];
    float* out = (float*)d_out;

    unsigned short *hab, *hsb, *Wqab, *Wkab, *Wqb, *Wkb, *Wvb;
    unsigned short *qab, *kab, *Qb, *Kb, *Vb, *Vt, *Att, *Shx;
    float *O, *S, *Wf, *rsum;
    cudaGetSymbolAddress((void**)&hab,  g_hab);
    cudaGetSymbolAddress((void**)&hsb,  g_hsb);
    cudaGetSymbolAddress((void**)&Wqab, g_Wqab);
    cudaGetSymbolAddress((void**)&Wkab, g_Wkab);
    cudaGetSymbolAddress((void**)&Wqb,  g_Wqb);
    cudaGetSymbolAddress((void**)&Wkb,  g_Wkb);
    cudaGetSymbolAddress((void**)&Wvb,  g_Wvb);
    cudaGetSymbolAddress((void**)&qab,  g_qab);
    cudaGetSymbolAddress((void**)&kab,  g_kab);
    cudaGetSymbolAddress((void**)&Qb,   g_Qb);
    cudaGetSymbolAddress((void**)&Kb,   g_Kb);
    cudaGetSymbolAddress((void**)&Vb,   g_Vb);
    cudaGetSymbolAddress((void**)&Vt,   g_Vt);
    cudaGetSymbolAddress((void**)&Att,  g_Att);
    cudaGetSymbolAddress((void**)&Shx,  g_Shx);
    cudaGetSymbolAddress((void**)&O,    g_O);
    cudaGetSymbolAddress((void**)&S,    g_S);
    cudaGetSymbolAddress((void**)&Wf,   g_Wf);
    cudaGetSymbolAddress((void**)&rsum, g_rsum);

    const int SM128 = NSTAGE * (128 * RSTR) * 2;               // 110592
    const int SM64  = NSTAGE * (64 * RSTR + 128 * RSTR);       // 82944

    static cudaStream_t s1;
    static cudaEvent_t e0, e1;
    static int inited = 0;
    if (!inited) {
        cudaStreamCreateWithFlags(&s1, cudaStreamNonBlocking);
        cudaEventCreateWithFlags(&e0, cudaEventDisableTiming);
        cudaEventCreateWithFlags(&e1, cudaEventDisableTiming);
        cudaFuncSetAttribute(gemm_nt_bf<64, unsigned short>,
                             cudaFuncAttributeMaxDynamicSharedMemorySize, SM64);
        cudaFuncSetAttribute(gemm_nt_bf<128, float>,
                             cudaFuncAttributeMaxDynamicSharedMemorySize, SM128);
        cudaFuncSetAttribute(gemm_nt_bf<64, float>,
                             cudaFuncAttributeMaxDynamicSharedMemorySize, SM64);
        cudaFuncSetAttribute(heads_gemm_bf,
                             cudaFuncAttributeMaxDynamicSharedMemorySize, SM128);
        inited = 1;
    }

    const dim3 blk(256);
    const dim3 gProj(DIM / 128, NTOK / 64);     // 6 x 48 = 288 CTAs (2/SM)
    const dim3 gNN(NTOK / 128, NTOK / 128);     // 24 x 24
    const dim3 gAV(DIM / 128, NTOK / 64);       // 6 x 48
    const int NH4 = (NTOK * DIM) / 4;
    const int NW4 = (DIM * DIM) / 4;

    cudaEventRecord(e0, 0);
    cudaStreamWaitEvent(s1, e0, 0);

    // ---- chain A (s1): structural attention weights ----
    zero_kernel<<<(NHEAD * NTOK + 255) / 256, 256, 0, s1>>>(rsum);
    f2b_multi<<<(NH4 + 2 * NW4 + 255) / 256, 256, 0, s1>>>(
        (const float4*)h_a, (uint2*)hab, NH4,
        (const float4*)Wq_a, (uint2*)Wqab, NW4,
        (const float4*)Wk_a, (uint2*)Wkab, NW4,
        nullptr, nullptr, 0);
    gemm_nt_bf<64, unsigned short><<<gProj, blk, SM64, s1>>>(hab, DIM, Wqab, DIM, qab, DIM, DIM, bq_a, 1.f);
    gemm_nt_bf<64, unsigned short><<<gProj, blk, SM64, s1>>>(hab, DIM, Wkab, DIM, kab, DIM, DIM, bk_a, 1.f);
    heads_gemm_bf<<<gNN, blk, SM128, s1>>>(qab, kab, Shx, rsum);
    wf_combine_kernel<<<NTOK, 384, 0, s1>>>(dep, rsum);
    cudaEventRecord(e1, s1);

    // ---- chain B (default): guided attention ----
    f2b_multi<<<(NH4 + 3 * NW4 + 255) / 256, 256>>>(
        (const float4*)h_s, (uint2*)hsb, NH4,
        (const float4*)Wq, (uint2*)Wqb, NW4,
        (const float4*)Wk, (uint2*)Wkb, NW4,
        (const float4*)Wv, (uint2*)Wvb, NW4);
    gemm_nt_bf<64, unsigned short><<<gProj, blk, SM64>>>(hsb, DIM, Wqb, DIM, Qb, DIM, DIM, bq, 1.f);
    gemm_nt_bf<64, unsigned short><<<gProj, blk, SM64>>>(hsb, DIM, Wkb, DIM, Kb, DIM, DIM, bk, 1.f);
    gemm_nt_bf<64, unsigned short><<<gProj, blk, SM64>>>(hsb, DIM, Wvb, DIM, Vb, DIM, DIM, bv, 1.f);
    transpose_v<<<dim3(DIM / 32, NTOK / 32), dim3(32, 8)>>>(Vb, Vt);
    const float score_scale = 1.f / sqrtf((float)DIM);
    gemm_nt_bf<128, float><<<gNN, blk, SM128>>>(Qb, DIM, Kb, DIM, S, NTOK, DIM, nullptr, score_scale);

    // join, then tail
    cudaStreamWaitEvent(0, e1, 0);
    masked_softmax_kernel<<<NTOK, 256>>>();
    gemm_nt_bf<64, float><<<gAV, blk, SM64>>>(Att, NTOK, Vt, NTOK, O, DIM, NTOK, nullptr, 1.f);
    ln_kernel<<<NTOK, 256>>>(h_s, lng, lnb, out);
}